// round 12
// baseline (speedup 1.0000x reference)
#include <cuda_runtime.h>
#include <cuda_bf16.h>
#include <math.h>
#include <stdint.h>

// Problem dims
#define BB 32
#define NN 577
#define CC 768
#define HH 3072
#define MROWS (BB*NN)            // 18464
#define NPAD 608                 // 577 padded to multiple of 32
#define OUT_X_ELEMS ((long long)MROWS*CC)
#define OUT_ATTN_ELEMS (BB*(NN-1))

// ---------------- helpers ----------------
__device__ __forceinline__ uint32_t smem_u32(const void* p) {
    uint32_t a;
    asm("{ .reg .u64 t; cvta.to.shared.u64 t, %1; cvt.u32.u64 %0, t; }" : "=r"(a) : "l"(p));
    return a;
}

#define LDSM_X4(r, a) \
    asm volatile("ldmatrix.sync.aligned.m8n8.x4.shared.b16 {%0,%1,%2,%3}, [%4];" \
        : "=r"((r)[0]),"=r"((r)[1]),"=r"((r)[2]),"=r"((r)[3]) : "r"(a))

__device__ __forceinline__ void mma16816(float* c, const uint32_t* a, const uint32_t* b) {
    asm volatile("mma.sync.aligned.m16n8k16.row.col.f32.bf16.bf16.f32 "
        "{%0,%1,%2,%3}, {%4,%5,%6,%7}, {%8,%9}, {%0,%1,%2,%3};"
        : "+f"(c[0]),"+f"(c[1]),"+f"(c[2]),"+f"(c[3])
        : "r"(a[0]),"r"(a[1]),"r"(a[2]),"r"(a[3]),"r"(b[0]),"r"(b[1]));
}

__device__ __forceinline__ void cp_async16(uint32_t dst, const void* src, int srcsz) {
    asm volatile("cp.async.cg.shared.global [%0], [%1], 16, %2;"
        :: "r"(dst), "l"(src), "r"(srcsz));
}
#define CP_COMMIT() asm volatile("cp.async.commit_group;")
#define CP_WAIT0()  asm volatile("cp.async.wait_group 0;")
#define CP_WAIT1()  asm volatile("cp.async.wait_group 1;")

// smem tile: 128 rows x 64B (32 bf16). XOR swizzle on 16B chunks.
__device__ __forceinline__ uint32_t swz_off(int row, int kc) {
    int c = kc ^ (row & 3) ^ ((row >> 2) & 1);
    return (uint32_t)(row * 64 + c * 16);
}

__device__ __forceinline__ void split_f(float v, __nv_bfloat16& h, __nv_bfloat16& l) {
    h = __float2bfloat16(v);
    l = __float2bfloat16(v - __bfloat162float(h));
}

// ---------------- scratch ----------------
__device__ __nv_bfloat16 g_h_hi[(size_t)MROWS*CC],   g_h_lo[(size_t)MROWS*CC];
__device__ __nv_bfloat16 g_wqkv_hi[(size_t)3*CC*CC], g_wqkv_lo[(size_t)3*CC*CC];
__device__ __nv_bfloat16 g_wproj_hi[(size_t)CC*CC],  g_wproj_lo[(size_t)CC*CC];
__device__ __nv_bfloat16 g_wfc1_hi[(size_t)HH*CC],   g_wfc1_lo[(size_t)HH*CC];
__device__ __nv_bfloat16 g_wfc2_hi[(size_t)CC*HH],   g_wfc2_lo[(size_t)CC*HH];
__device__ __nv_bfloat16 g_qk_hi[(size_t)MROWS*2*CC], g_qk_lo[(size_t)MROWS*2*CC];
__device__ __nv_bfloat16 g_attn_hi[(size_t)BB*NN*NPAD], g_attn_lo[(size_t)BB*NN*NPAD];
__device__ __nv_bfloat16 g_vT_hi[(size_t)BB*CC*NPAD],   g_vT_lo[(size_t)BB*CC*NPAD];
__device__ __nv_bfloat16 g_yt_hi[(size_t)MROWS*CC],  g_yt_lo[(size_t)MROWS*CC];
__device__ float         g_x2[(size_t)MROWS*CC];
__device__ __nv_bfloat16 g_m1_hi[(size_t)MROWS*CC],  g_m1_lo[(size_t)MROWS*CC];
__device__ __nv_bfloat16 g_f1_hi[(size_t)MROWS*HH],  g_f1_lo[(size_t)MROWS*HH];

// ============= mma.sync bf16x3 GEMM (8 warps, 64x32 warp tile, 3-stage) ====
#define STAGE_BYTES 32768
#define SMEM_BYTES  (3*STAGE_BYTES)

struct GemmP {
    const __nv_bfloat16 *Ah, *Al; int lda; long long sA;
    const __nv_bfloat16 *Bh, *Bl; int ldb; long long sB;
    float* Cf; __nv_bfloat16 *Ch, *Cl; int ldc; long long sC;
    int M, N, Npad, K;
    const float* bias; float alpha;
    const float* resid; long long sR;
};

template<bool GELU, bool RESID, bool WF32, bool WSPLIT>
__device__ __forceinline__ void gemm_body(const GemmP& p, int bx, int by, int bz,
                                          char* smem) {
    const uint32_t sbase = smem_u32(smem);
    const int tid = threadIdx.x;
    const int wid = tid >> 5, lane = tid & 31;
    const long long m0 = (long long)by * 128;
    const long long n0 = (long long)bx * 128;
    const int warp_m = (wid & 1) * 64;
    const int warp_n = (wid >> 1) * 32;

    const __nv_bfloat16* Ah = p.Ah + bz * p.sA;
    const __nv_bfloat16* Al = p.Al + bz * p.sA;
    const __nv_bfloat16* Bh = p.Bh + bz * p.sB;
    const __nv_bfloat16* Bl = p.Bl + bz * p.sB;
    const int M = p.M, N = p.N, Npad = p.Npad, K = p.K;
    const int lda = p.lda, ldb = p.ldb, ldc = p.ldc;

    const int nCh = K >> 5;

    float acc[4][4][4];
    #pragma unroll
    for (int i = 0; i < 4; i++)
        #pragma unroll
        for (int j = 0; j < 4; j++)
            #pragma unroll
            for (int e = 0; e < 4; e++) acc[i][j][e] = 0.f;

    auto load_stage = [&](int it) {
        const uint32_t sb = sbase + (uint32_t)(it % 3) * STAGE_BYTES;
        const long long k0 = (long long)it << 5;
        #pragma unroll
        for (int u = 0; u < 8; u++) {
            int idx = u * 256 + tid;
            int mat = idx >> 9;        // 0:Ah 1:Al 2:Bh 3:Bl
            int rem = idx & 511;
            int row = rem >> 2;
            int kc  = rem & 3;
            const __nv_bfloat16* src = (mat == 0) ? Ah : (mat == 1) ? Al
                                      : (mat == 2) ? Bh : Bl;
            long long r0 = (mat < 2) ? m0 : n0;
            int rt = (mat < 2) ? M : N;
            int ld = (mat < 2) ? lda : ldb;
            long long gr = r0 + row;
            int ok = (gr < rt) ? 16 : 0;
            const __nv_bfloat16* gp = src + (ok ? gr * (long long)ld : 0) + k0 + kc * 8;
            cp_async16(sb + (uint32_t)mat * 8192 + swz_off(row, kc), gp, ok);
        }
        CP_COMMIT();
    };

    auto compute_stage = [&](int it) {
        const uint32_t sb = sbase + (uint32_t)(it % 3) * STAGE_BYTES;
        #pragma unroll
        for (int ks = 0; ks < 2; ks++) {
            const int kc0 = ks * 2;
            uint32_t ah[4][4], al[4][4], bh[4][2], bl[4][2];
            const int arow = lane & 15;
            const int akc  = kc0 + (lane >> 4);
            #pragma unroll
            for (int i = 0; i < 4; i++) {
                uint32_t off = swz_off(warp_m + i * 16 + arow, akc);
                LDSM_X4(ah[i], sb + off);
                LDSM_X4(al[i], sb + 8192 + off);
            }
            const int brow = ((lane >> 4) << 3) + (lane & 7);
            const int bkc  = kc0 + ((lane >> 3) & 1);
            #pragma unroll
            for (int j = 0; j < 2; j++) {
                uint32_t r[4];
                uint32_t off = swz_off(warp_n + j * 16 + brow, bkc);
                LDSM_X4(r, sb + 16384 + off);
                bh[2*j][0] = r[0]; bh[2*j][1] = r[1];
                bh[2*j+1][0] = r[2]; bh[2*j+1][1] = r[3];
                LDSM_X4(r, sb + 24576 + off);
                bl[2*j][0] = r[0]; bl[2*j][1] = r[1];
                bl[2*j+1][0] = r[2]; bl[2*j+1][1] = r[3];
            }
            #pragma unroll
            for (int i = 0; i < 4; i++)
                #pragma unroll
                for (int j = 0; j < 4; j++)
                    mma16816(acc[i][j], ah[i], bh[j]);
            #pragma unroll
            for (int i = 0; i < 4; i++)
                #pragma unroll
                for (int j = 0; j < 4; j++)
                    mma16816(acc[i][j], ah[i], bl[j]);
            #pragma unroll
            for (int i = 0; i < 4; i++)
                #pragma unroll
                for (int j = 0; j < 4; j++)
                    mma16816(acc[i][j], al[i], bh[j]);
        }
    };

    load_stage(0);
    if (nCh > 1) load_stage(1);
    for (int it = 0; it < nCh; it++) {
        if (it + 1 < nCh) CP_WAIT1(); else CP_WAIT0();
        __syncthreads();
        if (it + 2 < nCh) load_stage(it + 2);
        compute_stage(it);
    }

    // ---- epilogue (paired stores when alignment allows) ----
    const int tm = lane >> 2;
    const int tn = (lane & 3) * 2;
    const bool evenld = ((ldc & 1) == 0) && ((p.sC & 1LL) == 0LL);
    #pragma unroll
    for (int i = 0; i < 4; i++) {
        #pragma unroll
        for (int half = 0; half < 2; half++) {
            long long m = m0 + warp_m + i * 16 + tm + half * 8;
            if (m >= M) continue;
            const long long base = (long long)bz * p.sC + m * (long long)ldc;
            #pragma unroll
            for (int j = 0; j < 4; j++) {
                long long n = n0 + warp_n + j * 8 + tn;
                if (n >= Npad) continue;
                float v0 = acc[i][j][half * 2];
                float v1 = acc[i][j][half * 2 + 1];
                if (n < N) {
                    if (p.bias) v0 += p.bias[n];
                    v0 *= p.alpha;
                    if (GELU) v0 = 0.5f * v0 * (1.0f + erff(v0 * 0.70710678118654752440f));
                    if (RESID) v0 += p.resid[(long long)bz * p.sR + m * (long long)ldc + n];
                } else v0 = 0.f;
                if (n + 1 < N) {
                    if (p.bias) v1 += p.bias[n + 1];
                    v1 *= p.alpha;
                    if (GELU) v1 = 0.5f * v1 * (1.0f + erff(v1 * 0.70710678118654752440f));
                    if (RESID) v1 += p.resid[(long long)bz * p.sR + m * (long long)ldc + n + 1];
                } else v1 = 0.f;
                const bool pair = evenld && (n + 1 < Npad);
                if (WF32) {
                    if (pair) *(float2*)(p.Cf + base + n) = make_float2(v0, v1);
                    else { p.Cf[base + n] = v0; if (n + 1 < Npad) p.Cf[base + n + 1] = v1; }
                }
                if (WSPLIT) {
                    __nv_bfloat16 h0, l0, h1, l1;
                    split_f(v0, h0, l0); split_f(v1, h1, l1);
                    if (pair) {
                        __nv_bfloat162 hp; hp.x = h0; hp.y = h1;
                        __nv_bfloat162 lp; lp.x = l0; lp.y = l1;
                        *(__nv_bfloat162*)(p.Ch + base + n) = hp;
                        *(__nv_bfloat162*)(p.Cl + base + n) = lp;
                    } else {
                        p.Ch[base + n] = h0; p.Cl[base + n] = l0;
                        if (n + 1 < Npad) { p.Ch[base + n + 1] = h1; p.Cl[base + n + 1] = l1; }
                    }
                }
            }
        }
    }
}

template<bool GELU, bool RESID, bool WF32, bool WSPLIT>
__global__ void __launch_bounds__(256, 2) mma_gemm(GemmP p) {
    extern __shared__ char smem[];
    gemm_body<GELU, RESID, WF32, WSPLIT>(p, blockIdx.x, blockIdx.y, blockIdx.z, smem);
}

// Fused dual GEMM: flat grid; blocks < n1 run p1, rest run p2. Same epilogue flags.
template<bool GELU, bool RESID, bool WF32, bool WSPLIT>
__global__ void __launch_bounds__(256, 2) mma_gemm_dual(
    GemmP p1, GemmP p2, int n1, int nx1, int ny1, int nx2, int ny2) {
    extern __shared__ char smem[];
    int bid = blockIdx.x;
    if (bid < n1) {
        gemm_body<GELU, RESID, WF32, WSPLIT>(
            p1, bid % nx1, (bid / nx1) % ny1, bid / (nx1 * ny1), smem);
    } else {
        int b = bid - n1;
        gemm_body<GELU, RESID, WF32, WSPLIT>(
            p2, b % nx2, (b / nx2) % ny2, b / (nx2 * ny2), smem);
    }
}

// ---------------- LayerNorm -> bf16 hi/lo (vectorized: float4 / bf16x2) ----
__global__ void ln_split_kernel(const float* __restrict__ x,
                                const float* __restrict__ w,
                                const float* __restrict__ b,
                                __nv_bfloat16* __restrict__ oh,
                                __nv_bfloat16* __restrict__ ol) {
    long long row = blockIdx.x;
    const float4* xr = (const float4*)(x + row * CC);
    float4 v4 = make_float4(0.f, 0.f, 0.f, 0.f);
    float s = 0.f, ss = 0.f;
    const int t = threadIdx.x;
    if (t < CC / 4) {
        v4 = xr[t];
        s  = v4.x + v4.y + v4.z + v4.w;
        ss = v4.x * v4.x + v4.y * v4.y + v4.z * v4.z + v4.w * v4.w;
    }
    __shared__ float r0[32], r1[32];
    #pragma unroll
    for (int o = 16; o > 0; o >>= 1) {
        s  += __shfl_xor_sync(0xffffffffu, s, o);
        ss += __shfl_xor_sync(0xffffffffu, ss, o);
    }
    int lane = t & 31, wd = t >> 5;
    if (lane == 0) { r0[wd] = s; r1[wd] = ss; }
    __syncthreads();
    int nw = blockDim.x >> 5;
    if (t < 32) {
        float a = (t < nw) ? r0[t] : 0.f;
        float c = (t < nw) ? r1[t] : 0.f;
        #pragma unroll
        for (int o = 16; o > 0; o >>= 1) {
            a += __shfl_xor_sync(0xffffffffu, a, o);
            c += __shfl_xor_sync(0xffffffffu, c, o);
        }
        if (t == 0) { r0[0] = a; r1[0] = c; }
    }
    __syncthreads();
    float mean = r0[0] / (float)CC;
    float inv = rsqrtf(r1[0] / (float)CC - mean * mean + 1e-5f);
    if (t < CC / 4) {
        float4 w4 = ((const float4*)w)[t];
        float4 b4 = ((const float4*)b)[t];
        float o0 = (v4.x - mean) * inv * w4.x + b4.x;
        float o1 = (v4.y - mean) * inv * w4.y + b4.y;
        float o2 = (v4.z - mean) * inv * w4.z + b4.z;
        float o3 = (v4.w - mean) * inv * w4.w + b4.w;
        __nv_bfloat16 h0,l0,h1,l1,h2,l2,h3,l3;
        split_f(o0,h0,l0); split_f(o1,h1,l1); split_f(o2,h2,l2); split_f(o3,h3,l3);
        long long base = row * CC + (long long)t * 4;
        __nv_bfloat162 hp0; hp0.x = h0; hp0.y = h1;
        __nv_bfloat162 hp1; hp1.x = h2; hp1.y = h3;
        __nv_bfloat162 lp0; lp0.x = l0; lp0.y = l1;
        __nv_bfloat162 lp1; lp1.x = l2; lp1.y = l3;
        *(__nv_bfloat162*)(oh + base)     = hp0;
        *(__nv_bfloat162*)(oh + base + 2) = hp1;
        *(__nv_bfloat162*)(ol + base)     = lp0;
        *(__nv_bfloat162*)(ol + base + 2) = lp1;
    }
}

// -------- softmax over hi/lo score rows, in place -> probs hi/lo + token slice
__global__ void softmax_split_kernel(__nv_bfloat16* __restrict__ sh,
                                     __nv_bfloat16* __restrict__ sl,
                                     float* __restrict__ tok) {
    long long row = blockIdx.x;
    __nv_bfloat16* rh = sh + row * NPAD;
    __nv_bfloat16* rl = sl + row * NPAD;
    int t = (int)(row % NN);
    int b = (int)(row / NN);
    __shared__ float buf[NN];
    __shared__ float red[32];
    int lane = threadIdx.x & 31, wd = threadIdx.x >> 5;
    int nw = blockDim.x >> 5;

    float mx = -1e30f;
    for (int i = threadIdx.x; i < NN; i += blockDim.x) {
        float v = __bfloat162float(rh[i]) + __bfloat162float(rl[i]);
        buf[i] = v; mx = fmaxf(mx, v);
    }
    #pragma unroll
    for (int o = 16; o > 0; o >>= 1) mx = fmaxf(mx, __shfl_xor_sync(0xffffffffu, mx, o));
    if (lane == 0) red[wd] = mx;
    __syncthreads();
    if (threadIdx.x < 32) {
        float v = (threadIdx.x < nw) ? red[threadIdx.x] : -1e30f;
        #pragma unroll
        for (int o = 16; o > 0; o >>= 1) v = fmaxf(v, __shfl_xor_sync(0xffffffffu, v, o));
        if (threadIdx.x == 0) red[0] = v;
    }
    __syncthreads();
    mx = red[0];
    __syncthreads();

    float s = 0.f;
    for (int i = threadIdx.x; i < NN; i += blockDim.x) {
        float e = expf(buf[i] - mx); buf[i] = e; s += e;
    }
    #pragma unroll
    for (int o = 16; o > 0; o >>= 1) s += __shfl_xor_sync(0xffffffffu, s, o);
    if (lane == 0) red[wd] = s;
    __syncthreads();
    if (threadIdx.x < 32) {
        float v = (threadIdx.x < nw) ? red[threadIdx.x] : 0.f;
        #pragma unroll
        for (int o = 16; o > 0; o >>= 1) v += __shfl_xor_sync(0xffffffffu, v, o);
        if (threadIdx.x == 0) red[0] = v;
    }
    __syncthreads();
    float inv = 1.0f / red[0];
    for (int i = threadIdx.x; i < NN; i += blockDim.x) {
        float v = buf[i] * inv;
        __nv_bfloat16 h, l; split_f(v, h, l);
        rh[i] = h; rl[i] = l;
        if (t == 0 && i >= 1) tok[(long long)b * (NN - 1) + (i - 1)] = v;
    }
}

// ---------------- merged weight split (vectorized, one launch) -------------
#define W0 ((long long)3*CC*CC)                  // qkv
#define W1 (W0 + (long long)CC*CC)               // +proj
#define W2 (W1 + (long long)HH*CC)               // +fc1
#define W3 (W2 + (long long)CC*HH)               // +fc2
__global__ void split_all_kernel(const float* __restrict__ qkv_w,
                                 const float* __restrict__ proj_w,
                                 const float* __restrict__ fc1_w,
                                 const float* __restrict__ fc2_w,
                                 __nv_bfloat16* __restrict__ qkv_h, __nv_bfloat16* __restrict__ qkv_l,
                                 __nv_bfloat16* __restrict__ proj_h, __nv_bfloat16* __restrict__ proj_l,
                                 __nv_bfloat16* __restrict__ fc1_h, __nv_bfloat16* __restrict__ fc1_l,
                                 __nv_bfloat16* __restrict__ fc2_h, __nv_bfloat16* __restrict__ fc2_l) {
    long long i4 = (long long)blockIdx.x * blockDim.x + threadIdx.x;
    if (i4 >= W3 / 4) return;
    long long i = i4 * 4;
    const float* src; __nv_bfloat16 *oh, *ol; long long off;
    if (i < W0)      { src = qkv_w;  oh = qkv_h;  ol = qkv_l;  off = i; }
    else if (i < W1) { src = proj_w; oh = proj_h; ol = proj_l; off = i - W0; }
    else if (i < W2) { src = fc1_w;  oh = fc1_h;  ol = fc1_l;  off = i - W1; }
    else             { src = fc2_w;  oh = fc2_h;  ol = fc2_l;  off = i - W2; }
    float4 v = *(const float4*)(src + off);
    __nv_bfloat16 h0,l0,h1,l1,h2,l2,h3,l3;
    split_f(v.x,h0,l0); split_f(v.y,h1,l1); split_f(v.z,h2,l2); split_f(v.w,h3,l3);
    __nv_bfloat162 hp0; hp0.x = h0; hp0.y = h1;
    __nv_bfloat162 hp1; hp1.x = h2; hp1.y = h3;
    __nv_bfloat162 lp0; lp0.x = l0; lp0.y = l1;
    __nv_bfloat162 lp1; lp1.x = l2; lp1.y = l3;
    *(__nv_bfloat162*)(oh + off)     = hp0;
    *(__nv_bfloat162*)(oh + off + 2) = hp1;
    *(__nv_bfloat162*)(ol + off)     = lp0;
    *(__nv_bfloat162*)(ol + off + 2) = lp1;
}

// ---------------- launch ----------------
extern "C" void kernel_launch(void* const* d_in, const int* in_sizes, int n_in,
                              void* d_out, int out_size) {
    const float* x       = (const float*)d_in[0];
    const float* norm1_w = (const float*)d_in[1];
    const float* norm1_b = (const float*)d_in[2];
    const float* qkv_w   = (const float*)d_in[3];
    const float* proj_w  = (const float*)d_in[4];
    const float* proj_b  = (const float*)d_in[5];
    const float* norm2_w = (const float*)d_in[6];
    const float* norm2_b = (const float*)d_in[7];
    const float* fc1_w   = (const float*)d_in[8];
    const float* fc1_b   = (const float*)d_in[9];
    const float* fc2_w   = (const float*)d_in[10];
    const float* fc2_b   = (const float*)d_in[11];

    float* out_x    = (float*)d_out;
    float* out_attn = out_x + OUT_X_ELEMS;

    __nv_bfloat16 *h_hi, *h_lo, *wqkv_hi, *wqkv_lo, *wproj_hi, *wproj_lo;
    __nv_bfloat16 *wfc1_hi, *wfc1_lo, *wfc2_hi, *wfc2_lo;
    __nv_bfloat16 *qk_hi, *qk_lo, *attn_hi, *attn_lo, *vT_hi, *vT_lo;
    __nv_bfloat16 *yt_hi, *yt_lo, *m1_hi, *m1_lo, *f1_hi, *f1_lo;
    float *x2;
    cudaGetSymbolAddress((void**)&h_hi, g_h_hi);   cudaGetSymbolAddress((void**)&h_lo, g_h_lo);
    cudaGetSymbolAddress((void**)&wqkv_hi, g_wqkv_hi); cudaGetSymbolAddress((void**)&wqkv_lo, g_wqkv_lo);
    cudaGetSymbolAddress((void**)&wproj_hi, g_wproj_hi); cudaGetSymbolAddress((void**)&wproj_lo, g_wproj_lo);
    cudaGetSymbolAddress((void**)&wfc1_hi, g_wfc1_hi); cudaGetSymbolAddress((void**)&wfc1_lo, g_wfc1_lo);
    cudaGetSymbolAddress((void**)&wfc2_hi, g_wfc2_hi); cudaGetSymbolAddress((void**)&wfc2_lo, g_wfc2_lo);
    cudaGetSymbolAddress((void**)&qk_hi, g_qk_hi); cudaGetSymbolAddress((void**)&qk_lo, g_qk_lo);
    cudaGetSymbolAddress((void**)&attn_hi, g_attn_hi); cudaGetSymbolAddress((void**)&attn_lo, g_attn_lo);
    cudaGetSymbolAddress((void**)&vT_hi, g_vT_hi); cudaGetSymbolAddress((void**)&vT_lo, g_vT_lo);
    cudaGetSymbolAddress((void**)&yt_hi, g_yt_hi); cudaGetSymbolAddress((void**)&yt_lo, g_yt_lo);
    cudaGetSymbolAddress((void**)&x2, g_x2);
    cudaGetSymbolAddress((void**)&m1_hi, g_m1_hi); cudaGetSymbolAddress((void**)&m1_lo, g_m1_lo);
    cudaGetSymbolAddress((void**)&f1_hi, g_f1_hi); cudaGetSymbolAddress((void**)&f1_lo, g_f1_lo);

    cudaFuncSetAttribute(mma_gemm<false,false,false,true>,      cudaFuncAttributeMaxDynamicSharedMemorySize, SMEM_BYTES);
    cudaFuncSetAttribute(mma_gemm<false,false,true,false>,      cudaFuncAttributeMaxDynamicSharedMemorySize, SMEM_BYTES);
    cudaFuncSetAttribute(mma_gemm<true,false,false,true>,       cudaFuncAttributeMaxDynamicSharedMemorySize, SMEM_BYTES);
    cudaFuncSetAttribute(mma_gemm<false,true,true,false>,       cudaFuncAttributeMaxDynamicSharedMemorySize, SMEM_BYTES);
    cudaFuncSetAttribute(mma_gemm_dual<false,false,false,true>, cudaFuncAttributeMaxDynamicSharedMemorySize, SMEM_BYTES);

    const float scale = 0.03608439182435161f; // 768^-0.5

    // 0) split all weights in one vectorized launch
    split_all_kernel<<<(int)((W3 / 4 + 255) / 256), 256>>>(
        qkv_w, proj_w, fc1_w, fc2_w,
        wqkv_hi, wqkv_lo, wproj_hi, wproj_lo,
        wfc1_hi, wfc1_lo, wfc2_hi, wfc2_lo);

    // 1) LN1 -> h hi/lo
    ln_split_kernel<<<MROWS, 256>>>(x, norm1_w, norm1_b, h_hi, h_lo);

    // 2) qk = h @ [wq;wk]^T  -> hi/lo  (N = 2*CC)
    {
        GemmP p = { h_hi, h_lo, CC, 0, wqkv_hi, wqkv_lo, CC, 0,
                    nullptr, qk_hi, qk_lo, 2*CC, 0,
                    MROWS, 2*CC, 2*CC, CC, nullptr, 1.f, nullptr, 0 };
        mma_gemm<false,false,false,true><<<dim3(12, 145, 1), 256, SMEM_BYTES>>>(p);
    }

    // 3+4) FUSED: scores = scale*q@k^T per batch (800 CTAs)
    //             vT[c,t] = w_v·h per batch (960 CTAs)  -> one 1760-CTA launch
    {
        GemmP pS = { qk_hi, qk_lo, 2*CC, (long long)NN*2*CC,
                     qk_hi + CC, qk_lo + CC, 2*CC, (long long)NN*2*CC,
                     nullptr, attn_hi, attn_lo, NPAD, (long long)NN*NPAD,
                     NN, NN, NPAD, CC, nullptr, scale, nullptr, 0 };
        GemmP pV = { wqkv_hi + (size_t)2*CC*CC, wqkv_lo + (size_t)2*CC*CC, CC, 0,
                     h_hi, h_lo, CC, (long long)NN*CC,
                     nullptr, vT_hi, vT_lo, NPAD, (long long)CC*NPAD,
                     CC, NN, NPAD, CC, nullptr, 1.f, nullptr, 0 };
        mma_gemm_dual<false,false,false,true><<<800 + 960, 256, SMEM_BYTES>>>(
            pS, pV, 800, 5, 5, 5, 6);
    }

    // 5) softmax over hi/lo rows in place + token_attn slice
    softmax_split_kernel<<<MROWS, 256>>>(attn_hi, attn_lo, out_attn);

    // 6) yt[c,t] = sum_m vT[c,m]·attnP[t,m] per batch -> hi/lo
    {
        GemmP p = { vT_hi, vT_lo, NPAD, (long long)CC*NPAD,
                    attn_hi, attn_lo, NPAD, (long long)NN*NPAD,
                    nullptr, yt_hi, yt_lo, NN, (long long)CC*NN,
                    CC, NN, NN, NPAD, nullptr, 1.f, nullptr, 0 };
        mma_gemm<false,false,false,true><<<dim3(5, 6, BB), 256, SMEM_BYTES>>>(p);
    }

    // 7) x2 = 2*(yt_flat @ proj_w^T + proj_b) -> f32
    {
        GemmP p = { yt_hi, yt_lo, CC, 0, wproj_hi, wproj_lo, CC, 0,
                    x2, nullptr, nullptr, CC, 0,
                    MROWS, CC, CC, CC, proj_b, 2.f, nullptr, 0 };
        mma_gemm<false,false,true,false><<<dim3(6, 145, 1), 256, SMEM_BYTES>>>(p);
    }

    // 8) LN2 -> m1 hi/lo
    ln_split_kernel<<<MROWS, 256>>>(x2, norm2_w, norm2_b, m1_hi, m1_lo);

    // 9) f1 = gelu(m1 @ fc1_w^T + fc1_b) -> hi/lo
    {
        GemmP p = { m1_hi, m1_lo, CC, 0, wfc1_hi, wfc1_lo, CC, 0,
                    nullptr, f1_hi, f1_lo, HH, 0,
                    MROWS, HH, HH, CC, fc1_b, 1.f, nullptr, 0 };
        mma_gemm<true,false,false,true><<<dim3(24, 145, 1), 256, SMEM_BYTES>>>(p);
    }

    // 10) out_x = x2 + f1 @ fc2_w^T + fc2_b
    {
        GemmP p = { f1_hi, f1_lo, HH, 0, wfc2_hi, wfc2_lo, HH, 0,
                    out_x, nullptr, nullptr, CC, 0,
                    MROWS, CC, CC, HH, fc2_b, 1.f, x2, 0 };
        mma_gemm<false,true,true,false><<<dim3(6, 145, 1), 256, SMEM_BYTES>>>(p);
    }
}

// round 13
// speedup vs baseline: 1.0228x; 1.0228x over previous
#include <cuda_runtime.h>
#include <cuda_bf16.h>
#include <math.h>
#include <stdint.h>

// Problem dims
#define BB 32
#define NN 577
#define CC 768
#define HH 3072
#define MROWS (BB*NN)            // 18464
#define NPAD 608                 // 577 padded to multiple of 32
#define OUT_X_ELEMS ((long long)MROWS*CC)
#define OUT_ATTN_ELEMS (BB*(NN-1))

// ---------------- helpers ----------------
__device__ __forceinline__ uint32_t smem_u32(const void* p) {
    uint32_t a;
    asm("{ .reg .u64 t; cvta.to.shared.u64 t, %1; cvt.u32.u64 %0, t; }" : "=r"(a) : "l"(p));
    return a;
}

#define LDSM_X4(r, a) \
    asm volatile("ldmatrix.sync.aligned.m8n8.x4.shared.b16 {%0,%1,%2,%3}, [%4];" \
        : "=r"((r)[0]),"=r"((r)[1]),"=r"((r)[2]),"=r"((r)[3]) : "r"(a))

__device__ __forceinline__ void mma16816(float* c, const uint32_t* a, const uint32_t* b) {
    asm volatile("mma.sync.aligned.m16n8k16.row.col.f32.bf16.bf16.f32 "
        "{%0,%1,%2,%3}, {%4,%5,%6,%7}, {%8,%9}, {%0,%1,%2,%3};"
        : "+f"(c[0]),"+f"(c[1]),"+f"(c[2]),"+f"(c[3])
        : "r"(a[0]),"r"(a[1]),"r"(a[2]),"r"(a[3]),"r"(b[0]),"r"(b[1]));
}

__device__ __forceinline__ void cp_async16(uint32_t dst, const void* src, int srcsz) {
    asm volatile("cp.async.cg.shared.global [%0], [%1], 16, %2;"
        :: "r"(dst), "l"(src), "r"(srcsz));
}
#define CP_COMMIT() asm volatile("cp.async.commit_group;")
#define CP_WAIT0()  asm volatile("cp.async.wait_group 0;")
#define CP_WAIT1()  asm volatile("cp.async.wait_group 1;")

// smem tile: 128 rows x 64B (32 bf16). XOR swizzle on 16B chunks.
__device__ __forceinline__ uint32_t swz_off(int row, int kc) {
    int c = kc ^ (row & 3) ^ ((row >> 2) & 1);
    return (uint32_t)(row * 64 + c * 16);
}

__device__ __forceinline__ void split_f(float v, __nv_bfloat16& h, __nv_bfloat16& l) {
    h = __float2bfloat16(v);
    l = __float2bfloat16(v - __bfloat162float(h));
}

// ---------------- scratch ----------------
__device__ __nv_bfloat16 g_h_hi[(size_t)MROWS*CC],   g_h_lo[(size_t)MROWS*CC];
__device__ __nv_bfloat16 g_wqkv_hi[(size_t)3*CC*CC], g_wqkv_lo[(size_t)3*CC*CC];
__device__ __nv_bfloat16 g_wproj_hi[(size_t)CC*CC],  g_wproj_lo[(size_t)CC*CC];
__device__ __nv_bfloat16 g_wfc1_hi[(size_t)HH*CC],   g_wfc1_lo[(size_t)HH*CC];
__device__ __nv_bfloat16 g_wfc2_hi[(size_t)CC*HH],   g_wfc2_lo[(size_t)CC*HH];
__device__ __nv_bfloat16 g_qk_hi[(size_t)MROWS*2*CC], g_qk_lo[(size_t)MROWS*2*CC];
__device__ __nv_bfloat16 g_attn_hi[(size_t)BB*NN*NPAD], g_attn_lo[(size_t)BB*NN*NPAD];
__device__ __nv_bfloat16 g_vT_hi[(size_t)BB*CC*NPAD],   g_vT_lo[(size_t)BB*CC*NPAD];
__device__ __nv_bfloat16 g_yt_hi[(size_t)MROWS*CC],  g_yt_lo[(size_t)MROWS*CC];
__device__ float         g_x2[(size_t)MROWS*CC];
__device__ __nv_bfloat16 g_m1_hi[(size_t)MROWS*CC],  g_m1_lo[(size_t)MROWS*CC];
__device__ __nv_bfloat16 g_f1_hi[(size_t)MROWS*HH],  g_f1_lo[(size_t)MROWS*HH];

// ============= mma.sync bf16x3 GEMM (8 warps, 64x32 warp tile, 3-stage) ====
#define STAGE_BYTES 32768
#define SMEM_BYTES  (3*STAGE_BYTES)

template<bool GELU, bool RESID, bool WF32, bool WSPLIT>
__global__ void __launch_bounds__(256, 2) mma_gemm(
    const __nv_bfloat16* __restrict__ Ah, const __nv_bfloat16* __restrict__ Al,
    int lda, long long sA,
    const __nv_bfloat16* __restrict__ Bh, const __nv_bfloat16* __restrict__ Bl,
    int ldb, long long sB,
    float* __restrict__ Cf, __nv_bfloat16* __restrict__ Ch, __nv_bfloat16* __restrict__ Cl,
    int ldc, long long sC,
    int M, int N, int Npad, int K,
    const float* __restrict__ bias, float alpha,
    const float* __restrict__ resid, long long sR)
{
    extern __shared__ char smem[];
    const uint32_t sbase = smem_u32(smem);
    const int tid = threadIdx.x;
    const int wid = tid >> 5, lane = tid & 31;
    const int bz = blockIdx.z;
    const long long m0 = (long long)blockIdx.y * 128;
    const long long n0 = (long long)blockIdx.x * 128;
    const int warp_m = (wid & 1) * 64;
    const int warp_n = (wid >> 1) * 32;

    Ah += bz * sA; Al += bz * sA;
    Bh += bz * sB; Bl += bz * sB;

    const int nCh = K >> 5;

    float acc[4][4][4];
    #pragma unroll
    for (int i = 0; i < 4; i++)
        #pragma unroll
        for (int j = 0; j < 4; j++)
            #pragma unroll
            for (int e = 0; e < 4; e++) acc[i][j][e] = 0.f;

    auto load_stage = [&](int it) {
        const uint32_t sb = sbase + (uint32_t)(it % 3) * STAGE_BYTES;
        const long long k0 = (long long)it << 5;
        #pragma unroll
        for (int u = 0; u < 8; u++) {
            int idx = u * 256 + tid;
            int mat = idx >> 9;        // 0:Ah 1:Al 2:Bh 3:Bl
            int rem = idx & 511;
            int row = rem >> 2;
            int kc  = rem & 3;
            const __nv_bfloat16* src = (mat == 0) ? Ah : (mat == 1) ? Al
                                      : (mat == 2) ? Bh : Bl;
            long long r0 = (mat < 2) ? m0 : n0;
            int rt = (mat < 2) ? M : N;
            int ld = (mat < 2) ? lda : ldb;
            long long gr = r0 + row;
            int ok = (gr < rt) ? 16 : 0;
            const __nv_bfloat16* gp = src + (ok ? gr * (long long)ld : 0) + k0 + kc * 8;
            cp_async16(sb + (uint32_t)mat * 8192 + swz_off(row, kc), gp, ok);
        }
        CP_COMMIT();
    };

    auto compute_stage = [&](int it) {
        const uint32_t sb = sbase + (uint32_t)(it % 3) * STAGE_BYTES;
        #pragma unroll
        for (int ks = 0; ks < 2; ks++) {
            const int kc0 = ks * 2;
            uint32_t ah[4][4], al[4][4], bh[4][2], bl[4][2];
            const int arow = lane & 15;
            const int akc  = kc0 + (lane >> 4);
            #pragma unroll
            for (int i = 0; i < 4; i++) {
                uint32_t off = swz_off(warp_m + i * 16 + arow, akc);
                LDSM_X4(ah[i], sb + off);
                LDSM_X4(al[i], sb + 8192 + off);
            }
            const int brow = ((lane >> 4) << 3) + (lane & 7);
            const int bkc  = kc0 + ((lane >> 3) & 1);
            #pragma unroll
            for (int j = 0; j < 2; j++) {
                uint32_t r[4];
                uint32_t off = swz_off(warp_n + j * 16 + brow, bkc);
                LDSM_X4(r, sb + 16384 + off);
                bh[2*j][0] = r[0]; bh[2*j][1] = r[1];
                bh[2*j+1][0] = r[2]; bh[2*j+1][1] = r[3];
                LDSM_X4(r, sb + 24576 + off);
                bl[2*j][0] = r[0]; bl[2*j][1] = r[1];
                bl[2*j+1][0] = r[2]; bl[2*j+1][1] = r[3];
            }
            #pragma unroll
            for (int i = 0; i < 4; i++)
                #pragma unroll
                for (int j = 0; j < 4; j++) {
                    mma16816(acc[i][j], ah[i], bh[j]);
                    mma16816(acc[i][j], ah[i], bl[j]);
                    mma16816(acc[i][j], al[i], bh[j]);
                }
        }
    };

    load_stage(0);
    if (nCh > 1) load_stage(1);
    for (int it = 0; it < nCh; it++) {
        if (it + 1 < nCh) CP_WAIT1(); else CP_WAIT0();
        __syncthreads();
        if (it + 2 < nCh) load_stage(it + 2);
        compute_stage(it);
    }

    // ---- epilogue (paired stores when alignment allows) ----
    const int tm = lane >> 2;
    const int tn = (lane & 3) * 2;
    const bool evenld = ((ldc & 1) == 0) && ((sC & 1LL) == 0LL);
    #pragma unroll
    for (int i = 0; i < 4; i++) {
        #pragma unroll
        for (int half = 0; half < 2; half++) {
            long long m = m0 + warp_m + i * 16 + tm + half * 8;
            if (m >= M) continue;
            const long long base = (long long)bz * sC + m * (long long)ldc;
            #pragma unroll
            for (int j = 0; j < 4; j++) {
                long long n = n0 + warp_n + j * 8 + tn;
                if (n >= Npad) continue;
                float v0 = acc[i][j][half * 2];
                float v1 = acc[i][j][half * 2 + 1];
                if (n < N) {
                    if (bias) v0 += bias[n];
                    v0 *= alpha;
                    if (GELU) v0 = 0.5f * v0 * (1.0f + erff(v0 * 0.70710678118654752440f));
                    if (RESID) v0 += resid[(long long)bz * sR + m * (long long)ldc + n];
                } else v0 = 0.f;
                if (n + 1 < N) {
                    if (bias) v1 += bias[n + 1];
                    v1 *= alpha;
                    if (GELU) v1 = 0.5f * v1 * (1.0f + erff(v1 * 0.70710678118654752440f));
                    if (RESID) v1 += resid[(long long)bz * sR + m * (long long)ldc + n + 1];
                } else v1 = 0.f;
                const bool pair = evenld && (n + 1 < Npad);
                if (WF32) {
                    if (pair) *(float2*)(Cf + base + n) = make_float2(v0, v1);
                    else { Cf[base + n] = v0; if (n + 1 < Npad) Cf[base + n + 1] = v1; }
                }
                if (WSPLIT) {
                    __nv_bfloat16 h0, l0, h1, l1;
                    split_f(v0, h0, l0); split_f(v1, h1, l1);
                    if (pair) {
                        __nv_bfloat162 hp; hp.x = h0; hp.y = h1;
                        __nv_bfloat162 lp; lp.x = l0; lp.y = l1;
                        *(__nv_bfloat162*)(Ch + base + n) = hp;
                        *(__nv_bfloat162*)(Cl + base + n) = lp;
                    } else {
                        Ch[base + n] = h0; Cl[base + n] = l0;
                        if (n + 1 < Npad) { Ch[base + n + 1] = h1; Cl[base + n + 1] = l1; }
                    }
                }
            }
        }
    }
}

// ---------------- LayerNorm -> bf16 hi/lo (vectorized: float4 / bf16x2) ----
__global__ void ln_split_kernel(const float* __restrict__ x,
                                const float* __restrict__ w,
                                const float* __restrict__ b,
                                __nv_bfloat16* __restrict__ oh,
                                __nv_bfloat16* __restrict__ ol) {
    long long row = blockIdx.x;
    const float4* xr = (const float4*)(x + row * CC);
    float4 v4 = make_float4(0.f, 0.f, 0.f, 0.f);
    float s = 0.f, ss = 0.f;
    const int t = threadIdx.x;
    if (t < CC / 4) {
        v4 = xr[t];
        s  = v4.x + v4.y + v4.z + v4.w;
        ss = v4.x * v4.x + v4.y * v4.y + v4.z * v4.z + v4.w * v4.w;
    }
    __shared__ float r0[32], r1[32];
    #pragma unroll
    for (int o = 16; o > 0; o >>= 1) {
        s  += __shfl_xor_sync(0xffffffffu, s, o);
        ss += __shfl_xor_sync(0xffffffffu, ss, o);
    }
    int lane = t & 31, wd = t >> 5;
    if (lane == 0) { r0[wd] = s; r1[wd] = ss; }
    __syncthreads();
    int nw = blockDim.x >> 5;
    if (t < 32) {
        float a = (t < nw) ? r0[t] : 0.f;
        float c = (t < nw) ? r1[t] : 0.f;
        #pragma unroll
        for (int o = 16; o > 0; o >>= 1) {
            a += __shfl_xor_sync(0xffffffffu, a, o);
            c += __shfl_xor_sync(0xffffffffu, c, o);
        }
        if (t == 0) { r0[0] = a; r1[0] = c; }
    }
    __syncthreads();
    float mean = r0[0] / (float)CC;
    float inv = rsqrtf(r1[0] / (float)CC - mean * mean + 1e-5f);
    if (t < CC / 4) {
        float4 w4 = ((const float4*)w)[t];
        float4 b4 = ((const float4*)b)[t];
        float o0 = (v4.x - mean) * inv * w4.x + b4.x;
        float o1 = (v4.y - mean) * inv * w4.y + b4.y;
        float o2 = (v4.z - mean) * inv * w4.z + b4.z;
        float o3 = (v4.w - mean) * inv * w4.w + b4.w;
        __nv_bfloat16 h0,l0,h1,l1,h2,l2,h3,l3;
        split_f(o0,h0,l0); split_f(o1,h1,l1); split_f(o2,h2,l2); split_f(o3,h3,l3);
        long long base = row * CC + (long long)t * 4;
        __nv_bfloat162 hp0; hp0.x = h0; hp0.y = h1;
        __nv_bfloat162 hp1; hp1.x = h2; hp1.y = h3;
        __nv_bfloat162 lp0; lp0.x = l0; lp0.y = l1;
        __nv_bfloat162 lp1; lp1.x = l2; lp1.y = l3;
        *(__nv_bfloat162*)(oh + base)     = hp0;
        *(__nv_bfloat162*)(oh + base + 2) = hp1;
        *(__nv_bfloat162*)(ol + base)     = lp0;
        *(__nv_bfloat162*)(ol + base + 2) = lp1;
    }
}

// -------- softmax over hi/lo score rows, in place, bf16x2-vectorized I/O ----
// Rows are NPAD(608)-strided so each row base is 4B-aligned; elements [0,576)
// are processed as 288 bf16x2 pairs; element 576 is the scalar tail.
__global__ void softmax_split_kernel(__nv_bfloat16* __restrict__ sh,
                                     __nv_bfloat16* __restrict__ sl,
                                     float* __restrict__ tok) {
    long long row = blockIdx.x;
    __nv_bfloat162* rh2 = (__nv_bfloat162*)(sh + row * NPAD);
    __nv_bfloat162* rl2 = (__nv_bfloat162*)(sl + row * NPAD);
    __nv_bfloat16* rh = sh + row * NPAD;
    __nv_bfloat16* rl = sl + row * NPAD;
    int t = (int)(row % NN);
    int b = (int)(row / NN);
    __shared__ float buf[NN];
    __shared__ float red[32];
    int lane = threadIdx.x & 31, wd = threadIdx.x >> 5;
    int nw = blockDim.x >> 5;

    const int PAIRS = (NN - 1) / 2;   // 288
    float mx = -1e30f;
    for (int i = threadIdx.x; i < PAIRS; i += blockDim.x) {
        __nv_bfloat162 h2 = rh2[i];
        __nv_bfloat162 l2 = rl2[i];
        float a = __bfloat162float(h2.x) + __bfloat162float(l2.x);
        float c = __bfloat162float(h2.y) + __bfloat162float(l2.y);
        buf[2*i] = a; buf[2*i+1] = c;
        mx = fmaxf(mx, fmaxf(a, c));
    }
    if (threadIdx.x == 0) {
        float v = __bfloat162float(rh[NN-1]) + __bfloat162float(rl[NN-1]);
        buf[NN-1] = v; mx = fmaxf(mx, v);
    }
    #pragma unroll
    for (int o = 16; o > 0; o >>= 1) mx = fmaxf(mx, __shfl_xor_sync(0xffffffffu, mx, o));
    if (lane == 0) red[wd] = mx;
    __syncthreads();
    if (threadIdx.x < 32) {
        float v = (threadIdx.x < nw) ? red[threadIdx.x] : -1e30f;
        #pragma unroll
        for (int o = 16; o > 0; o >>= 1) v = fmaxf(v, __shfl_xor_sync(0xffffffffu, v, o));
        if (threadIdx.x == 0) red[0] = v;
    }
    __syncthreads();
    mx = red[0];
    __syncthreads();

    float s = 0.f;
    for (int i = threadIdx.x; i < NN; i += blockDim.x) {
        float e = expf(buf[i] - mx); buf[i] = e; s += e;
    }
    #pragma unroll
    for (int o = 16; o > 0; o >>= 1) s += __shfl_xor_sync(0xffffffffu, s, o);
    if (lane == 0) red[wd] = s;
    __syncthreads();
    if (threadIdx.x < 32) {
        float v = (threadIdx.x < nw) ? red[threadIdx.x] : 0.f;
        #pragma unroll
        for (int o = 16; o > 0; o >>= 1) v += __shfl_xor_sync(0xffffffffu, v, o);
        if (threadIdx.x == 0) red[0] = v;
    }
    __syncthreads();
    float inv = 1.0f / red[0];
    for (int i = threadIdx.x; i < PAIRS; i += blockDim.x) {
        float a = buf[2*i] * inv;
        float c = buf[2*i+1] * inv;
        __nv_bfloat16 ha, la, hc, lc;
        split_f(a, ha, la); split_f(c, hc, lc);
        __nv_bfloat162 hp; hp.x = ha; hp.y = hc;
        __nv_bfloat162 lp; lp.x = la; lp.y = lc;
        rh2[i] = hp; rl2[i] = lp;
        if (t == 0) {
            // tok index = element index - 1; elements 2i and 2i+1
            if (2*i >= 1) tok[(long long)b * (NN - 1) + (2*i - 1)] = a;
            tok[(long long)b * (NN - 1) + (2*i)] = c;
        }
    }
    if (threadIdx.x == 0) {
        float v = buf[NN-1] * inv;
        __nv_bfloat16 h, l; split_f(v, h, l);
        rh[NN-1] = h; rl[NN-1] = l;
        if (t == 0) tok[(long long)b * (NN - 1) + (NN - 2)] = v;
    }
}

// ---------------- merged weight split (vectorized, one launch) -------------
#define W0 ((long long)3*CC*CC)                  // qkv
#define W1 (W0 + (long long)CC*CC)               // +proj
#define W2 (W1 + (long long)HH*CC)               // +fc1
#define W3 (W2 + (long long)CC*HH)               // +fc2
__global__ void split_all_kernel(const float* __restrict__ qkv_w,
                                 const float* __restrict__ proj_w,
                                 const float* __restrict__ fc1_w,
                                 const float* __restrict__ fc2_w,
                                 __nv_bfloat16* __restrict__ qkv_h, __nv_bfloat16* __restrict__ qkv_l,
                                 __nv_bfloat16* __restrict__ proj_h, __nv_bfloat16* __restrict__ proj_l,
                                 __nv_bfloat16* __restrict__ fc1_h, __nv_bfloat16* __restrict__ fc1_l,
                                 __nv_bfloat16* __restrict__ fc2_h, __nv_bfloat16* __restrict__ fc2_l) {
    long long i4 = (long long)blockIdx.x * blockDim.x + threadIdx.x;
    if (i4 >= W3 / 4) return;
    long long i = i4 * 4;
    const float* src; __nv_bfloat16 *oh, *ol; long long off;
    if (i < W0)      { src = qkv_w;  oh = qkv_h;  ol = qkv_l;  off = i; }
    else if (i < W1) { src = proj_w; oh = proj_h; ol = proj_l; off = i - W0; }
    else if (i < W2) { src = fc1_w;  oh = fc1_h;  ol = fc1_l;  off = i - W1; }
    else             { src = fc2_w;  oh = fc2_h;  ol = fc2_l;  off = i - W2; }
    float4 v = *(const float4*)(src + off);
    __nv_bfloat16 h0,l0,h1,l1,h2,l2,h3,l3;
    split_f(v.x,h0,l0); split_f(v.y,h1,l1); split_f(v.z,h2,l2); split_f(v.w,h3,l3);
    __nv_bfloat162 hp0; hp0.x = h0; hp0.y = h1;
    __nv_bfloat162 hp1; hp1.x = h2; hp1.y = h3;
    __nv_bfloat162 lp0; lp0.x = l0; lp0.y = l1;
    __nv_bfloat162 lp1; lp1.x = l2; lp1.y = l3;
    *(__nv_bfloat162*)(oh + off)     = hp0;
    *(__nv_bfloat162*)(oh + off + 2) = hp1;
    *(__nv_bfloat162*)(ol + off)     = lp0;
    *(__nv_bfloat162*)(ol + off + 2) = lp1;
}

// ---------------- launch ----------------
extern "C" void kernel_launch(void* const* d_in, const int* in_sizes, int n_in,
                              void* d_out, int out_size) {
    const float* x       = (const float*)d_in[0];
    const float* norm1_w = (const float*)d_in[1];
    const float* norm1_b = (const float*)d_in[2];
    const float* qkv_w   = (const float*)d_in[3];
    const float* proj_w  = (const float*)d_in[4];
    const float* proj_b  = (const float*)d_in[5];
    const float* norm2_w = (const float*)d_in[6];
    const float* norm2_b = (const float*)d_in[7];
    const float* fc1_w   = (const float*)d_in[8];
    const float* fc1_b   = (const float*)d_in[9];
    const float* fc2_w   = (const float*)d_in[10];
    const float* fc2_b   = (const float*)d_in[11];

    float* out_x    = (float*)d_out;
    float* out_attn = out_x + OUT_X_ELEMS;

    __nv_bfloat16 *h_hi, *h_lo, *wqkv_hi, *wqkv_lo, *wproj_hi, *wproj_lo;
    __nv_bfloat16 *wfc1_hi, *wfc1_lo, *wfc2_hi, *wfc2_lo;
    __nv_bfloat16 *qk_hi, *qk_lo, *attn_hi, *attn_lo, *vT_hi, *vT_lo;
    __nv_bfloat16 *yt_hi, *yt_lo, *m1_hi, *m1_lo, *f1_hi, *f1_lo;
    float *x2;
    cudaGetSymbolAddress((void**)&h_hi, g_h_hi);   cudaGetSymbolAddress((void**)&h_lo, g_h_lo);
    cudaGetSymbolAddress((void**)&wqkv_hi, g_wqkv_hi); cudaGetSymbolAddress((void**)&wqkv_lo, g_wqkv_lo);
    cudaGetSymbolAddress((void**)&wproj_hi, g_wproj_hi); cudaGetSymbolAddress((void**)&wproj_lo, g_wproj_lo);
    cudaGetSymbolAddress((void**)&wfc1_hi, g_wfc1_hi); cudaGetSymbolAddress((void**)&wfc1_lo, g_wfc1_lo);
    cudaGetSymbolAddress((void**)&wfc2_hi, g_wfc2_hi); cudaGetSymbolAddress((void**)&wfc2_lo, g_wfc2_lo);
    cudaGetSymbolAddress((void**)&qk_hi, g_qk_hi); cudaGetSymbolAddress((void**)&qk_lo, g_qk_lo);
    cudaGetSymbolAddress((void**)&attn_hi, g_attn_hi); cudaGetSymbolAddress((void**)&attn_lo, g_attn_lo);
    cudaGetSymbolAddress((void**)&vT_hi, g_vT_hi); cudaGetSymbolAddress((void**)&vT_lo, g_vT_lo);
    cudaGetSymbolAddress((void**)&yt_hi, g_yt_hi); cudaGetSymbolAddress((void**)&yt_lo, g_yt_lo);
    cudaGetSymbolAddress((void**)&x2, g_x2);
    cudaGetSymbolAddress((void**)&m1_hi, g_m1_hi); cudaGetSymbolAddress((void**)&m1_lo, g_m1_lo);
    cudaGetSymbolAddress((void**)&f1_hi, g_f1_hi); cudaGetSymbolAddress((void**)&f1_lo, g_f1_lo);

    cudaFuncSetAttribute(mma_gemm<false,false,false,true>,  cudaFuncAttributeMaxDynamicSharedMemorySize, SMEM_BYTES);
    cudaFuncSetAttribute(mma_gemm<false,false,true,false>,  cudaFuncAttributeMaxDynamicSharedMemorySize, SMEM_BYTES);
    cudaFuncSetAttribute(mma_gemm<true,false,false,true>,   cudaFuncAttributeMaxDynamicSharedMemorySize, SMEM_BYTES);
    cudaFuncSetAttribute(mma_gemm<false,true,true,false>,   cudaFuncAttributeMaxDynamicSharedMemorySize, SMEM_BYTES);

    const float scale = 0.03608439182435161f; // 768^-0.5

    // 0) split all weights in one vectorized launch
    split_all_kernel<<<(int)((W3 / 4 + 255) / 256), 256>>>(
        qkv_w, proj_w, fc1_w, fc2_w,
        wqkv_hi, wqkv_lo, wproj_hi, wproj_lo,
        wfc1_hi, wfc1_lo, wfc2_hi, wfc2_lo);

    // 1) LN1 -> h hi/lo
    ln_split_kernel<<<MROWS, 256>>>(x, norm1_w, norm1_b, h_hi, h_lo);

    // 2) qk = h @ [wq;wk]^T  -> hi/lo  (N = 2*CC)
    mma_gemm<false,false,false,true><<<dim3(12, 145, 1), 256, SMEM_BYTES>>>(
        h_hi, h_lo, CC, 0, wqkv_hi, wqkv_lo, CC, 0,
        nullptr, qk_hi, qk_lo, 2*CC, 0,
        MROWS, 2*CC, 2*CC, CC, nullptr, 1.f, nullptr, 0);

    // 3) vT[c,t] = w_v[c,:]·h[t,:] per batch -> hi/lo, columns padded to NPAD
    mma_gemm<false,false,false,true><<<dim3(5, 6, BB), 256, SMEM_BYTES>>>(
        wqkv_hi + (size_t)2*CC*CC, wqkv_lo + (size_t)2*CC*CC, CC, 0,
        h_hi, h_lo, CC, (long long)NN*CC,
        nullptr, vT_hi, vT_lo, NPAD, (long long)CC*NPAD,
        CC, NN, NPAD, CC, nullptr, 1.f, nullptr, 0);

    // 4) scores = scale * q @ k^T per batch -> bf16 hi/lo (pads zero-filled)
    mma_gemm<false,false,false,true><<<dim3(5, 5, BB), 256, SMEM_BYTES>>>(
        qk_hi, qk_lo, 2*CC, (long long)NN*2*CC,
        qk_hi + CC, qk_lo + CC, 2*CC, (long long)NN*2*CC,
        nullptr, attn_hi, attn_lo, NPAD, (long long)NN*NPAD,
        NN, NN, NPAD, CC, nullptr, scale, nullptr, 0);

    // 5) softmax over hi/lo rows in place + token_attn slice
    softmax_split_kernel<<<MROWS, 256>>>(attn_hi, attn_lo, out_attn);

    // 6) yt[c,t] = sum_m vT[c,m]·attnP[t,m] per batch -> hi/lo ([CC][NN] dense)
    mma_gemm<false,false,false,true><<<dim3(5, 6, BB), 256, SMEM_BYTES>>>(
        vT_hi, vT_lo, NPAD, (long long)CC*NPAD,
        attn_hi, attn_lo, NPAD, (long long)NN*NPAD,
        nullptr, yt_hi, yt_lo, NN, (long long)CC*NN,
        CC, NN, NN, NPAD, nullptr, 1.f, nullptr, 0);

    // 7) x2 = 2*(yt_flat @ proj_w^T + proj_b) -> f32
    mma_gemm<false,false,true,false><<<dim3(6, 145, 1), 256, SMEM_BYTES>>>(
        yt_hi, yt_lo, CC, 0, wproj_hi, wproj_lo, CC, 0,
        x2, nullptr, nullptr, CC, 0,
        MROWS, CC, CC, CC, proj_b, 2.f, nullptr, 0);

    // 8) LN2 -> m1 hi/lo
    ln_split_kernel<<<MROWS, 256>>>(x2, norm2_w, norm2_b, m1_hi, m1_lo);

    // 9) f1 = gelu(m1 @ fc1_w^T + fc1_b) -> hi/lo
    mma_gemm<true,false,false,true><<<dim3(24, 145, 1), 256, SMEM_BYTES>>>(
        m1_hi, m1_lo, CC, 0, wfc1_hi, wfc1_lo, CC, 0,
        nullptr, f1_hi, f1_lo, HH, 0,
        MROWS, HH, HH, CC, fc1_b, 1.f, nullptr, 0);

    // 10) out_x = x2 + f1 @ fc2_w^T + fc2_b
    mma_gemm<false,true,true,false><<<dim3(6, 145, 1), 256, SMEM_BYTES>>>(
        f1_hi, f1_lo, HH, 0, wfc2_hi, wfc2_lo, HH, 0,
        out_x, nullptr, nullptr, CC, 0,
        MROWS, CC, CC, HH, fc2_b, 1.f, x2, 0);
}

// round 14
// speedup vs baseline: 1.0333x; 1.0103x over previous
#include <cuda_runtime.h>
#include <cuda_bf16.h>
#include <math.h>
#include <stdint.h>

// Problem dims
#define BB 32
#define NN 577
#define CC 768
#define HH 3072
#define MROWS (BB*NN)            // 18464
#define NPAD 608                 // 577 padded to multiple of 32
#define OUT_X_ELEMS ((long long)MROWS*CC)
#define OUT_ATTN_ELEMS (BB*(NN-1))

// ---------------- helpers ----------------
__device__ __forceinline__ uint32_t smem_u32(const void* p) {
    uint32_t a;
    asm("{ .reg .u64 t; cvta.to.shared.u64 t, %1; cvt.u32.u64 %0, t; }" : "=r"(a) : "l"(p));
    return a;
}

#define LDSM_X4(r, a) \
    asm volatile("ldmatrix.sync.aligned.m8n8.x4.shared.b16 {%0,%1,%2,%3}, [%4];" \
        : "=r"((r)[0]),"=r"((r)[1]),"=r"((r)[2]),"=r"((r)[3]) : "r"(a))

__device__ __forceinline__ void mma16816(float* c, const uint32_t* a, const uint32_t* b) {
    asm volatile("mma.sync.aligned.m16n8k16.row.col.f32.bf16.bf16.f32 "
        "{%0,%1,%2,%3}, {%4,%5,%6,%7}, {%8,%9}, {%0,%1,%2,%3};"
        : "+f"(c[0]),"+f"(c[1]),"+f"(c[2]),"+f"(c[3])
        : "r"(a[0]),"r"(a[1]),"r"(a[2]),"r"(a[3]),"r"(b[0]),"r"(b[1]));
}

__device__ __forceinline__ void cp_async16(uint32_t dst, const void* src, int srcsz) {
    asm volatile("cp.async.cg.shared.global [%0], [%1], 16, %2;"
        :: "r"(dst), "l"(src), "r"(srcsz));
}
#define CP_COMMIT() asm volatile("cp.async.commit_group;")
#define CP_WAIT0()  asm volatile("cp.async.wait_group 0;")
#define CP_WAIT1()  asm volatile("cp.async.wait_group 1;")

// smem tile: 128 rows x 64B (32 bf16). XOR swizzle on 16B chunks.
__device__ __forceinline__ uint32_t swz_off(int row, int kc) {
    int c = kc ^ (row & 3) ^ ((row >> 2) & 1);
    return (uint32_t)(row * 64 + c * 16);
}

__device__ __forceinline__ void split_f(float v, __nv_bfloat16& h, __nv_bfloat16& l) {
    h = __float2bfloat16(v);
    l = __float2bfloat16(v - __bfloat162float(h));
}

// ---------------- scratch ----------------
__device__ __nv_bfloat16 g_h_hi[(size_t)MROWS*CC],   g_h_lo[(size_t)MROWS*CC];
__device__ __nv_bfloat16 g_wqkv_hi[(size_t)3*CC*CC], g_wqkv_lo[(size_t)3*CC*CC];
__device__ __nv_bfloat16 g_wproj_hi[(size_t)CC*CC],  g_wproj_lo[(size_t)CC*CC];
__device__ __nv_bfloat16 g_wfc1_hi[(size_t)HH*CC],   g_wfc1_lo[(size_t)HH*CC];
__device__ __nv_bfloat16 g_wfc2_hi[(size_t)CC*HH],   g_wfc2_lo[(size_t)CC*HH];
__device__ __nv_bfloat16 g_qk_hi[(size_t)MROWS*2*CC], g_qk_lo[(size_t)MROWS*2*CC];
__device__ __nv_bfloat16 g_attn_hi[(size_t)BB*NN*NPAD], g_attn_lo[(size_t)BB*NN*NPAD];
__device__ __nv_bfloat16 g_vT_hi[(size_t)BB*CC*NPAD],   g_vT_lo[(size_t)BB*CC*NPAD];
__device__ __nv_bfloat16 g_yt_hi[(size_t)MROWS*CC],  g_yt_lo[(size_t)MROWS*CC];
__device__ float         g_x2[(size_t)MROWS*CC];
__device__ __nv_bfloat16 g_m1_hi[(size_t)MROWS*CC],  g_m1_lo[(size_t)MROWS*CC];
__device__ __nv_bfloat16 g_f1_hi[(size_t)MROWS*HH],  g_f1_lo[(size_t)MROWS*HH];

// ============= mma.sync bf16x3 GEMM (8 warps, 64x32 warp tile, 3-stage) ====
#define STAGE_BYTES 32768
#define SMEM_BYTES  (3*STAGE_BYTES)

template<bool GELU, bool RESID, bool WF32, bool WSPLIT>
__global__ void __launch_bounds__(256, 2) mma_gemm(
    const __nv_bfloat16* __restrict__ Ah, const __nv_bfloat16* __restrict__ Al,
    int lda, long long sA,
    const __nv_bfloat16* __restrict__ Bh, const __nv_bfloat16* __restrict__ Bl,
    int ldb, long long sB,
    float* __restrict__ Cf, __nv_bfloat16* __restrict__ Ch, __nv_bfloat16* __restrict__ Cl,
    int ldc, long long sC,
    int M, int N, int Npad, int K,
    const float* __restrict__ bias, float alpha,
    const float* __restrict__ resid, long long sR)
{
    extern __shared__ char smem[];
    const uint32_t sbase = smem_u32(smem);
    const int tid = threadIdx.x;
    const int wid = tid >> 5, lane = tid & 31;
    const int bz = blockIdx.z;
    const long long m0 = (long long)blockIdx.y * 128;
    const long long n0 = (long long)blockIdx.x * 128;
    const int warp_m = (wid & 1) * 64;
    const int warp_n = (wid >> 1) * 32;

    Ah += bz * sA; Al += bz * sA;
    Bh += bz * sB; Bl += bz * sB;

    const int nCh = K >> 5;

    float acc[4][4][4];
    #pragma unroll
    for (int i = 0; i < 4; i++)
        #pragma unroll
        for (int j = 0; j < 4; j++)
            #pragma unroll
            for (int e = 0; e < 4; e++) acc[i][j][e] = 0.f;

    auto load_stage = [&](int it) {
        const uint32_t sb = sbase + (uint32_t)(it % 3) * STAGE_BYTES;
        const long long k0 = (long long)it << 5;
        #pragma unroll
        for (int u = 0; u < 8; u++) {
            int idx = u * 256 + tid;
            int mat = idx >> 9;        // 0:Ah 1:Al 2:Bh 3:Bl
            int rem = idx & 511;
            int row = rem >> 2;
            int kc  = rem & 3;
            const __nv_bfloat16* src = (mat == 0) ? Ah : (mat == 1) ? Al
                                      : (mat == 2) ? Bh : Bl;
            long long r0 = (mat < 2) ? m0 : n0;
            int rt = (mat < 2) ? M : N;
            int ld = (mat < 2) ? lda : ldb;
            long long gr = r0 + row;
            int ok = (gr < rt) ? 16 : 0;
            const __nv_bfloat16* gp = src + (ok ? gr * (long long)ld : 0) + k0 + kc * 8;
            cp_async16(sb + (uint32_t)mat * 8192 + swz_off(row, kc), gp, ok);
        }
        CP_COMMIT();
    };

    auto compute_stage = [&](int it) {
        const uint32_t sb = sbase + (uint32_t)(it % 3) * STAGE_BYTES;
        #pragma unroll
        for (int ks = 0; ks < 2; ks++) {
            const int kc0 = ks * 2;
            uint32_t ah[4][4], al[4][4], bh[4][2], bl[4][2];
            const int arow = lane & 15;
            const int akc  = kc0 + (lane >> 4);
            #pragma unroll
            for (int i = 0; i < 4; i++) {
                uint32_t off = swz_off(warp_m + i * 16 + arow, akc);
                LDSM_X4(ah[i], sb + off);
                LDSM_X4(al[i], sb + 8192 + off);
            }
            const int brow = ((lane >> 4) << 3) + (lane & 7);
            const int bkc  = kc0 + ((lane >> 3) & 1);
            #pragma unroll
            for (int j = 0; j < 2; j++) {
                uint32_t r[4];
                uint32_t off = swz_off(warp_n + j * 16 + brow, bkc);
                LDSM_X4(r, sb + 16384 + off);
                bh[2*j][0] = r[0]; bh[2*j][1] = r[1];
                bh[2*j+1][0] = r[2]; bh[2*j+1][1] = r[3];
                LDSM_X4(r, sb + 24576 + off);
                bl[2*j][0] = r[0]; bl[2*j][1] = r[1];
                bl[2*j+1][0] = r[2]; bl[2*j+1][1] = r[3];
            }
            #pragma unroll
            for (int i = 0; i < 4; i++)
                #pragma unroll
                for (int j = 0; j < 4; j++) {
                    mma16816(acc[i][j], ah[i], bh[j]);
                    mma16816(acc[i][j], ah[i], bl[j]);
                    mma16816(acc[i][j], al[i], bh[j]);
                }
        }
    };

    load_stage(0);
    if (nCh > 1) load_stage(1);
    for (int it = 0; it < nCh; it++) {
        if (it + 1 < nCh) CP_WAIT1(); else CP_WAIT0();
        __syncthreads();
        if (it + 2 < nCh) load_stage(it + 2);
        compute_stage(it);
    }

    // ---- epilogue (paired stores/loads when alignment allows) ----
    const int tm = lane >> 2;
    const int tn = (lane & 3) * 2;
    const bool evenld = ((ldc & 1) == 0) && ((sC & 1LL) == 0LL);
    #pragma unroll
    for (int i = 0; i < 4; i++) {
        #pragma unroll
        for (int half = 0; half < 2; half++) {
            long long m = m0 + warp_m + i * 16 + tm + half * 8;
            if (m >= M) continue;
            const long long base = (long long)bz * sC + m * (long long)ldc;
            #pragma unroll
            for (int j = 0; j < 4; j++) {
                long long n = n0 + warp_n + j * 8 + tn;
                if (n >= Npad) continue;
                float v0 = acc[i][j][half * 2];
                float v1 = acc[i][j][half * 2 + 1];
                const bool pair = evenld && (n + 1 < Npad);
                float r0v = 0.f, r1v = 0.f;
                if (RESID) {
                    const long long rbase = (long long)bz * sR + m * (long long)ldc;
                    if (pair && (n + 1 < N)) {
                        float2 rv = *(const float2*)(resid + rbase + n);
                        r0v = rv.x; r1v = rv.y;
                    } else {
                        if (n < N) r0v = resid[rbase + n];
                        if (n + 1 < N) r1v = resid[rbase + n + 1];
                    }
                }
                if (n < N) {
                    if (bias) v0 += bias[n];
                    v0 *= alpha;
                    if (GELU) v0 = 0.5f * v0 * (1.0f + erff(v0 * 0.70710678118654752440f));
                    if (RESID) v0 += r0v;
                } else v0 = 0.f;
                if (n + 1 < N) {
                    if (bias) v1 += bias[n + 1];
                    v1 *= alpha;
                    if (GELU) v1 = 0.5f * v1 * (1.0f + erff(v1 * 0.70710678118654752440f));
                    if (RESID) v1 += r1v;
                } else v1 = 0.f;
                if (WF32) {
                    if (pair) *(float2*)(Cf + base + n) = make_float2(v0, v1);
                    else { Cf[base + n] = v0; if (n + 1 < Npad) Cf[base + n + 1] = v1; }
                }
                if (WSPLIT) {
                    __nv_bfloat16 h0, l0, h1, l1;
                    split_f(v0, h0, l0); split_f(v1, h1, l1);
                    if (pair) {
                        __nv_bfloat162 hp; hp.x = h0; hp.y = h1;
                        __nv_bfloat162 lp; lp.x = l0; lp.y = l1;
                        *(__nv_bfloat162*)(Ch + base + n) = hp;
                        *(__nv_bfloat162*)(Cl + base + n) = lp;
                    } else {
                        Ch[base + n] = h0; Cl[base + n] = l0;
                        if (n + 1 < Npad) { Ch[base + n + 1] = h1; Cl[base + n + 1] = l1; }
                    }
                }
            }
        }
    }
}

// ---------------- LayerNorm -> bf16 hi/lo (192 threads, float4 / bf16x2) ----
__global__ void ln_split_kernel(const float* __restrict__ x,
                                const float* __restrict__ w,
                                const float* __restrict__ b,
                                __nv_bfloat16* __restrict__ oh,
                                __nv_bfloat16* __restrict__ ol) {
    long long row = blockIdx.x;
    const float4* xr = (const float4*)(x + row * CC);
    const int t = threadIdx.x;              // 0..191, one float4 each
    float4 v4 = xr[t];
    float s  = v4.x + v4.y + v4.z + v4.w;
    float ss = v4.x * v4.x + v4.y * v4.y + v4.z * v4.z + v4.w * v4.w;
    __shared__ float r0[32], r1[32];
    #pragma unroll
    for (int o = 16; o > 0; o >>= 1) {
        s  += __shfl_xor_sync(0xffffffffu, s, o);
        ss += __shfl_xor_sync(0xffffffffu, ss, o);
    }
    int lane = t & 31, wd = t >> 5;
    if (lane == 0) { r0[wd] = s; r1[wd] = ss; }
    __syncthreads();
    int nw = blockDim.x >> 5;   // 6
    if (t < 32) {
        float a = (t < nw) ? r0[t] : 0.f;
        float c = (t < nw) ? r1[t] : 0.f;
        #pragma unroll
        for (int o = 16; o > 0; o >>= 1) {
            a += __shfl_xor_sync(0xffffffffu, a, o);
            c += __shfl_xor_sync(0xffffffffu, c, o);
        }
        if (t == 0) { r0[0] = a; r1[0] = c; }
    }
    __syncthreads();
    float mean = r0[0] / (float)CC;
    float inv = rsqrtf(r1[0] / (float)CC - mean * mean + 1e-5f);
    {
        float4 w4 = ((const float4*)w)[t];
        float4 b4 = ((const float4*)b)[t];
        float o0 = (v4.x - mean) * inv * w4.x + b4.x;
        float o1 = (v4.y - mean) * inv * w4.y + b4.y;
        float o2 = (v4.z - mean) * inv * w4.z + b4.z;
        float o3 = (v4.w - mean) * inv * w4.w + b4.w;
        __nv_bfloat16 h0,l0,h1,l1,h2,l2,h3,l3;
        split_f(o0,h0,l0); split_f(o1,h1,l1); split_f(o2,h2,l2); split_f(o3,h3,l3);
        long long base = row * CC + (long long)t * 4;
        __nv_bfloat162 hp0; hp0.x = h0; hp0.y = h1;
        __nv_bfloat162 hp1; hp1.x = h2; hp1.y = h3;
        __nv_bfloat162 lp0; lp0.x = l0; lp0.y = l1;
        __nv_bfloat162 lp1; lp1.x = l2; lp1.y = l3;
        *(__nv_bfloat162*)(oh + base)     = hp0;
        *(__nv_bfloat162*)(oh + base + 2) = hp1;
        *(__nv_bfloat162*)(ol + base)     = lp0;
        *(__nv_bfloat162*)(ol + base + 2) = lp1;
    }
}

// -------- softmax over hi/lo score rows (288 threads: one bf16x2 pair each) --
__global__ void softmax_split_kernel(__nv_bfloat16* __restrict__ sh,
                                     __nv_bfloat16* __restrict__ sl,
                                     float* __restrict__ tok) {
    long long row = blockIdx.x;
    __nv_bfloat162* rh2 = (__nv_bfloat162*)(sh + row * NPAD);
    __nv_bfloat162* rl2 = (__nv_bfloat162*)(sl + row * NPAD);
    __nv_bfloat16* rh = sh + row * NPAD;
    __nv_bfloat16* rl = sl + row * NPAD;
    int t = (int)(row % NN);
    int b = (int)(row / NN);
    __shared__ float buf[NN];
    __shared__ float red[32];
    const int tx = threadIdx.x;              // 0..287
    int lane = tx & 31, wd = tx >> 5;
    int nw = blockDim.x >> 5;                // 9

    float a, c;
    {
        __nv_bfloat162 h2 = rh2[tx];
        __nv_bfloat162 l2 = rl2[tx];
        a = __bfloat162float(h2.x) + __bfloat162float(l2.x);
        c = __bfloat162float(h2.y) + __bfloat162float(l2.y);
        buf[2*tx] = a; buf[2*tx+1] = c;
    }
    float mx = fmaxf(a, c);
    if (tx == 0) {
        float v = __bfloat162float(rh[NN-1]) + __bfloat162float(rl[NN-1]);
        buf[NN-1] = v; mx = fmaxf(mx, v);
    }
    #pragma unroll
    for (int o = 16; o > 0; o >>= 1) mx = fmaxf(mx, __shfl_xor_sync(0xffffffffu, mx, o));
    if (lane == 0) red[wd] = mx;
    __syncthreads();
    if (tx < 32) {
        float v = (tx < nw) ? red[tx] : -1e30f;
        #pragma unroll
        for (int o = 16; o > 0; o >>= 1) v = fmaxf(v, __shfl_xor_sync(0xffffffffu, v, o));
        if (tx == 0) red[0] = v;
    }
    __syncthreads();
    mx = red[0];
    __syncthreads();

    float s = 0.f;
    for (int i = tx; i < NN; i += blockDim.x) {
        float e = expf(buf[i] - mx); buf[i] = e; s += e;
    }
    #pragma unroll
    for (int o = 16; o > 0; o >>= 1) s += __shfl_xor_sync(0xffffffffu, s, o);
    if (lane == 0) red[wd] = s;
    __syncthreads();
    if (tx < 32) {
        float v = (tx < nw) ? red[tx] : 0.f;
        #pragma unroll
        for (int o = 16; o > 0; o >>= 1) v += __shfl_xor_sync(0xffffffffu, v, o);
        if (tx == 0) red[0] = v;
    }
    __syncthreads();
    float inv = 1.0f / red[0];
    {
        float pa = buf[2*tx] * inv;
        float pc = buf[2*tx+1] * inv;
        __nv_bfloat16 ha, la, hc, lc;
        split_f(pa, ha, la); split_f(pc, hc, lc);
        __nv_bfloat162 hp; hp.x = ha; hp.y = hc;
        __nv_bfloat162 lp; lp.x = la; lp.y = lc;
        rh2[tx] = hp; rl2[tx] = lp;
        if (t == 0) {
            if (2*tx >= 1) tok[(long long)b * (NN - 1) + (2*tx - 1)] = pa;
            tok[(long long)b * (NN - 1) + (2*tx)] = pc;
        }
    }
    if (tx == 0) {
        float v = buf[NN-1] * inv;
        __nv_bfloat16 h, l; split_f(v, h, l);
        rh[NN-1] = h; rl[NN-1] = l;
        if (t == 0) tok[(long long)b * (NN - 1) + (NN - 2)] = v;
    }
}

// ---------------- merged weight split (vectorized, one launch) -------------
#define W0 ((long long)3*CC*CC)                  // qkv
#define W1 (W0 + (long long)CC*CC)               // +proj
#define W2 (W1 + (long long)HH*CC)               // +fc1
#define W3 (W2 + (long long)CC*HH)               // +fc2
__global__ void split_all_kernel(const float* __restrict__ qkv_w,
                                 const float* __restrict__ proj_w,
                                 const float* __restrict__ fc1_w,
                                 const float* __restrict__ fc2_w,
                                 __nv_bfloat16* __restrict__ qkv_h, __nv_bfloat16* __restrict__ qkv_l,
                                 __nv_bfloat16* __restrict__ proj_h, __nv_bfloat16* __restrict__ proj_l,
                                 __nv_bfloat16* __restrict__ fc1_h, __nv_bfloat16* __restrict__ fc1_l,
                                 __nv_bfloat16* __restrict__ fc2_h, __nv_bfloat16* __restrict__ fc2_l) {
    long long i4 = (long long)blockIdx.x * blockDim.x + threadIdx.x;
    if (i4 >= W3 / 4) return;
    long long i = i4 * 4;
    const float* src; __nv_bfloat16 *oh, *ol; long long off;
    if (i < W0)      { src = qkv_w;  oh = qkv_h;  ol = qkv_l;  off = i; }
    else if (i < W1) { src = proj_w; oh = proj_h; ol = proj_l; off = i - W0; }
    else if (i < W2) { src = fc1_w;  oh = fc1_h;  ol = fc1_l;  off = i - W1; }
    else             { src = fc2_w;  oh = fc2_h;  ol = fc2_l;  off = i - W2; }
    float4 v = *(const float4*)(src + off);
    __nv_bfloat16 h0,l0,h1,l1,h2,l2,h3,l3;
    split_f(v.x,h0,l0); split_f(v.y,h1,l1); split_f(v.z,h2,l2); split_f(v.w,h3,l3);
    __nv_bfloat162 hp0; hp0.x = h0; hp0.y = h1;
    __nv_bfloat162 hp1; hp1.x = h2; hp1.y = h3;
    __nv_bfloat162 lp0; lp0.x = l0; lp0.y = l1;
    __nv_bfloat162 lp1; lp1.x = l2; lp1.y = l3;
    *(__nv_bfloat162*)(oh + off)     = hp0;
    *(__nv_bfloat162*)(oh + off + 2) = hp1;
    *(__nv_bfloat162*)(ol + off)     = lp0;
    *(__nv_bfloat162*)(ol + off + 2) = lp1;
}

// ---------------- launch ----------------
extern "C" void kernel_launch(void* const* d_in, const int* in_sizes, int n_in,
                              void* d_out, int out_size) {
    const float* x       = (const float*)d_in[0];
    const float* norm1_w = (const float*)d_in[1];
    const float* norm1_b = (const float*)d_in[2];
    const float* qkv_w   = (const float*)d_in[3];
    const float* proj_w  = (const float*)d_in[4];
    const float* proj_b  = (const float*)d_in[5];
    const float* norm2_w = (const float*)d_in[6];
    const float* norm2_b = (const float*)d_in[7];
    const float* fc1_w   = (const float*)d_in[8];
    const float* fc1_b   = (const float*)d_in[9];
    const float* fc2_w   = (const float*)d_in[10];
    const float* fc2_b   = (const float*)d_in[11];

    float* out_x    = (float*)d_out;
    float* out_attn = out_x + OUT_X_ELEMS;

    __nv_bfloat16 *h_hi, *h_lo, *wqkv_hi, *wqkv_lo, *wproj_hi, *wproj_lo;
    __nv_bfloat16 *wfc1_hi, *wfc1_lo, *wfc2_hi, *wfc2_lo;
    __nv_bfloat16 *qk_hi, *qk_lo, *attn_hi, *attn_lo, *vT_hi, *vT_lo;
    __nv_bfloat16 *yt_hi, *yt_lo, *m1_hi, *m1_lo, *f1_hi, *f1_lo;
    float *x2;
    cudaGetSymbolAddress((void**)&h_hi, g_h_hi);   cudaGetSymbolAddress((void**)&h_lo, g_h_lo);
    cudaGetSymbolAddress((void**)&wqkv_hi, g_wqkv_hi); cudaGetSymbolAddress((void**)&wqkv_lo, g_wqkv_lo);
    cudaGetSymbolAddress((void**)&wproj_hi, g_wproj_hi); cudaGetSymbolAddress((void**)&wproj_lo, g_wproj_lo);
    cudaGetSymbolAddress((void**)&wfc1_hi, g_wfc1_hi); cudaGetSymbolAddress((void**)&wfc1_lo, g_wfc1_lo);
    cudaGetSymbolAddress((void**)&wfc2_hi, g_wfc2_hi); cudaGetSymbolAddress((void**)&wfc2_lo, g_wfc2_lo);
    cudaGetSymbolAddress((void**)&qk_hi, g_qk_hi); cudaGetSymbolAddress((void**)&qk_lo, g_qk_lo);
    cudaGetSymbolAddress((void**)&attn_hi, g_attn_hi); cudaGetSymbolAddress((void**)&attn_lo, g_attn_lo);
    cudaGetSymbolAddress((void**)&vT_hi, g_vT_hi); cudaGetSymbolAddress((void**)&vT_lo, g_vT_lo);
    cudaGetSymbolAddress((void**)&yt_hi, g_yt_hi); cudaGetSymbolAddress((void**)&yt_lo, g_yt_lo);
    cudaGetSymbolAddress((void**)&x2, g_x2);
    cudaGetSymbolAddress((void**)&m1_hi, g_m1_hi); cudaGetSymbolAddress((void**)&m1_lo, g_m1_lo);
    cudaGetSymbolAddress((void**)&f1_hi, g_f1_hi); cudaGetSymbolAddress((void**)&f1_lo, g_f1_lo);

    cudaFuncSetAttribute(mma_gemm<false,false,false,true>,  cudaFuncAttributeMaxDynamicSharedMemorySize, SMEM_BYTES);
    cudaFuncSetAttribute(mma_gemm<false,false,true,false>,  cudaFuncAttributeMaxDynamicSharedMemorySize, SMEM_BYTES);
    cudaFuncSetAttribute(mma_gemm<true,false,false,true>,   cudaFuncAttributeMaxDynamicSharedMemorySize, SMEM_BYTES);
    cudaFuncSetAttribute(mma_gemm<false,true,true,false>,   cudaFuncAttributeMaxDynamicSharedMemorySize, SMEM_BYTES);

    const float scale = 0.03608439182435161f; // 768^-0.5

    // 0) split all weights in one vectorized launch
    split_all_kernel<<<(int)((W3 / 4 + 255) / 256), 256>>>(
        qkv_w, proj_w, fc1_w, fc2_w,
        wqkv_hi, wqkv_lo, wproj_hi, wproj_lo,
        wfc1_hi, wfc1_lo, wfc2_hi, wfc2_lo);

    // 1) LN1 -> h hi/lo (192 threads: exactly CC/4 float4 lanes)
    ln_split_kernel<<<MROWS, 192>>>(x, norm1_w, norm1_b, h_hi, h_lo);

    // 2) qk = h @ [wq;wk]^T  -> hi/lo  (N = 2*CC)
    mma_gemm<false,false,false,true><<<dim3(12, 145, 1), 256, SMEM_BYTES>>>(
        h_hi, h_lo, CC, 0, wqkv_hi, wqkv_lo, CC, 0,
        nullptr, qk_hi, qk_lo, 2*CC, 0,
        MROWS, 2*CC, 2*CC, CC, nullptr, 1.f, nullptr, 0);

    // 3) vT[c,t] = w_v[c,:]·h[t,:] per batch -> hi/lo, columns padded to NPAD
    mma_gemm<false,false,false,true><<<dim3(5, 6, BB), 256, SMEM_BYTES>>>(
        wqkv_hi + (size_t)2*CC*CC, wqkv_lo + (size_t)2*CC*CC, CC, 0,
        h_hi, h_lo, CC, (long long)NN*CC,
        nullptr, vT_hi, vT_lo, NPAD, (long long)CC*NPAD,
        CC, NN, NPAD, CC, nullptr, 1.f, nullptr, 0);

    // 4) scores = scale * q @ k^T per batch -> bf16 hi/lo (pads zero-filled)
    mma_gemm<false,false,false,true><<<dim3(5, 5, BB), 256, SMEM_BYTES>>>(
        qk_hi, qk_lo, 2*CC, (long long)NN*2*CC,
        qk_hi + CC, qk_lo + CC, 2*CC, (long long)NN*2*CC,
        nullptr, attn_hi, attn_lo, NPAD, (long long)NN*NPAD,
        NN, NN, NPAD, CC, nullptr, scale, nullptr, 0);

    // 5) softmax over hi/lo rows in place + token_attn slice (288 threads)
    softmax_split_kernel<<<MROWS, 288>>>(attn_hi, attn_lo, out_attn);

    // 6) yt[c,t] = sum_m vT[c,m]·attnP[t,m] per batch -> hi/lo ([CC][NN] dense)
    mma_gemm<false,false,false,true><<<dim3(5, 6, BB), 256, SMEM_BYTES>>>(
        vT_hi, vT_lo, NPAD, (long long)CC*NPAD,
        attn_hi, attn_lo, NPAD, (long long)NN*NPAD,
        nullptr, yt_hi, yt_lo, NN, (long long)CC*NN,
        CC, NN, NN, NPAD, nullptr, 1.f, nullptr, 0);

    // 7) x2 = 2*(yt_flat @ proj_w^T + proj_b) -> f32
    mma_gemm<false,false,true,false><<<dim3(6, 145, 1), 256, SMEM_BYTES>>>(
        yt_hi, yt_lo, CC, 0, wproj_hi, wproj_lo, CC, 0,
        x2, nullptr, nullptr, CC, 0,
        MROWS, CC, CC, CC, proj_b, 2.f, nullptr, 0);

    // 8) LN2 -> m1 hi/lo
    ln_split_kernel<<<MROWS, 192>>>(x2, norm2_w, norm2_b, m1_hi, m1_lo);

    // 9) f1 = gelu(m1 @ fc1_w^T + fc1_b) -> hi/lo
    mma_gemm<true,false,false,true><<<dim3(24, 145, 1), 256, SMEM_BYTES>>>(
        m1_hi, m1_lo, CC, 0, wfc1_hi, wfc1_lo, CC, 0,
        nullptr, f1_hi, f1_lo, HH, 0,
        MROWS, HH, HH, CC, fc1_b, 1.f, nullptr, 0);

    // 10) out_x = x2 + f1 @ fc2_w^T + fc2_b
    mma_gemm<false,true,true,false><<<dim3(6, 145, 1), 256, SMEM_BYTES>>>(
        f1_hi, f1_lo, HH, 0, wfc2_hi, wfc2_lo, HH, 0,
        out_x, nullptr, nullptr, CC, 0,
        MROWS, CC, CC, HH, fc2_b, 1.f, x2, 0);
}

// round 15
// speedup vs baseline: 1.0371x; 1.0038x over previous
#include <cuda_runtime.h>
#include <cuda_bf16.h>
#include <math.h>
#include <stdint.h>

// Problem dims
#define BB 32
#define NN 577
#define CC 768
#define HH 3072
#define MROWS (BB*NN)            // 18464
#define NPAD 608                 // 577 padded to multiple of 32
#define OUT_X_ELEMS ((long long)MROWS*CC)
#define OUT_ATTN_ELEMS (BB*(NN-1))

// ---------------- helpers ----------------
__device__ __forceinline__ uint32_t smem_u32(const void* p) {
    uint32_t a;
    asm("{ .reg .u64 t; cvta.to.shared.u64 t, %1; cvt.u32.u64 %0, t; }" : "=r"(a) : "l"(p));
    return a;
}

#define LDSM_X4(r, a) \
    asm volatile("ldmatrix.sync.aligned.m8n8.x4.shared.b16 {%0,%1,%2,%3}, [%4];" \
        : "=r"((r)[0]),"=r"((r)[1]),"=r"((r)[2]),"=r"((r)[3]) : "r"(a))

__device__ __forceinline__ void mma16816(float* c, const uint32_t* a, const uint32_t* b) {
    asm volatile("mma.sync.aligned.m16n8k16.row.col.f32.bf16.bf16.f32 "
        "{%0,%1,%2,%3}, {%4,%5,%6,%7}, {%8,%9}, {%0,%1,%2,%3};"
        : "+f"(c[0]),"+f"(c[1]),"+f"(c[2]),"+f"(c[3])
        : "r"(a[0]),"r"(a[1]),"r"(a[2]),"r"(a[3]),"r"(b[0]),"r"(b[1]));
}

__device__ __forceinline__ void cp_async16(uint32_t dst, const void* src, int srcsz) {
    asm volatile("cp.async.cg.shared.global [%0], [%1], 16, %2;"
        :: "r"(dst), "l"(src), "r"(srcsz));
}
#define CP_COMMIT() asm volatile("cp.async.commit_group;")
#define CP_WAIT0()  asm volatile("cp.async.wait_group 0;")
#define CP_WAIT1()  asm volatile("cp.async.wait_group 1;")

// smem tile: 128 rows x 64B (32 bf16). XOR swizzle on 16B chunks.
__device__ __forceinline__ uint32_t swz_off(int row, int kc) {
    int c = kc ^ (row & 3) ^ ((row >> 2) & 1);
    return (uint32_t)(row * 64 + c * 16);
}

__device__ __forceinline__ void split_f(float v, __nv_bfloat16& h, __nv_bfloat16& l) {
    h = __float2bfloat16(v);
    l = __float2bfloat16(v - __bfloat162float(h));
}

// ---------------- scratch ----------------
__device__ __nv_bfloat16 g_h_hi[(size_t)MROWS*CC],   g_h_lo[(size_t)MROWS*CC];
__device__ __nv_bfloat16 g_wqkv_hi[(size_t)3*CC*CC], g_wqkv_lo[(size_t)3*CC*CC];
__device__ __nv_bfloat16 g_wproj_hi[(size_t)CC*CC],  g_wproj_lo[(size_t)CC*CC];
__device__ __nv_bfloat16 g_wfc1_hi[(size_t)HH*CC],   g_wfc1_lo[(size_t)HH*CC];
__device__ __nv_bfloat16 g_wfc2_hi[(size_t)CC*HH],   g_wfc2_lo[(size_t)CC*HH];
__device__ __nv_bfloat16 g_qk_hi[(size_t)MROWS*2*CC], g_qk_lo[(size_t)MROWS*2*CC];
__device__ __nv_bfloat16 g_attn_hi[(size_t)BB*NN*NPAD], g_attn_lo[(size_t)BB*NN*NPAD];
__device__ __nv_bfloat16 g_vT_hi[(size_t)BB*CC*NPAD],   g_vT_lo[(size_t)BB*CC*NPAD];
__device__ __nv_bfloat16 g_yt_hi[(size_t)MROWS*CC],  g_yt_lo[(size_t)MROWS*CC];
__device__ float         g_x2[(size_t)MROWS*CC];
__device__ __nv_bfloat16 g_m1_hi[(size_t)MROWS*CC],  g_m1_lo[(size_t)MROWS*CC];
__device__ __nv_bfloat16 g_f1_hi[(size_t)MROWS*HH],  g_f1_lo[(size_t)MROWS*HH];

// ============= mma.sync bf16x3 GEMM (8 warps, 64x32 warp tile, 3-stage) ====
#define STAGE_BYTES 32768
#define SMEM_BYTES  (3*STAGE_BYTES)

template<bool GELU, bool RESID, bool WF32, bool WSPLIT>
__global__ void __launch_bounds__(256, 2) mma_gemm(
    const __nv_bfloat16* __restrict__ Ah, const __nv_bfloat16* __restrict__ Al,
    int lda, long long sA,
    const __nv_bfloat16* __restrict__ Bh, const __nv_bfloat16* __restrict__ Bl,
    int ldb, long long sB,
    float* __restrict__ Cf, __nv_bfloat16* __restrict__ Ch, __nv_bfloat16* __restrict__ Cl,
    int ldc, long long sC,
    int M, int N, int Npad, int K,
    const float* __restrict__ bias, float alpha,
    const float* __restrict__ resid, long long sR)
{
    extern __shared__ char smem[];
    const uint32_t sbase = smem_u32(smem);
    const int tid = threadIdx.x;
    const int wid = tid >> 5, lane = tid & 31;
    const int bz = blockIdx.z;
    const long long m0 = (long long)blockIdx.y * 128;
    const long long n0 = (long long)blockIdx.x * 128;
    const int warp_m = (wid & 1) * 64;
    const int warp_n = (wid >> 1) * 32;

    Ah += bz * sA; Al += bz * sA;
    Bh += bz * sB; Bl += bz * sB;

    const int nCh = K >> 5;

    float acc[4][4][4];
    #pragma unroll
    for (int i = 0; i < 4; i++)
        #pragma unroll
        for (int j = 0; j < 4; j++)
            #pragma unroll
            for (int e = 0; e < 4; e++) acc[i][j][e] = 0.f;

    auto load_stage = [&](int it) {
        const uint32_t sb = sbase + (uint32_t)(it % 3) * STAGE_BYTES;
        const long long k0 = (long long)it << 5;
        #pragma unroll
        for (int u = 0; u < 8; u++) {
            int idx = u * 256 + tid;
            int mat = idx >> 9;        // 0:Ah 1:Al 2:Bh 3:Bl
            int rem = idx & 511;
            int row = rem >> 2;
            int kc  = rem & 3;
            const __nv_bfloat16* src = (mat == 0) ? Ah : (mat == 1) ? Al
                                      : (mat == 2) ? Bh : Bl;
            long long r0 = (mat < 2) ? m0 : n0;
            int rt = (mat < 2) ? M : N;
            int ld = (mat < 2) ? lda : ldb;
            long long gr = r0 + row;
            int ok = (gr < rt) ? 16 : 0;
            const __nv_bfloat16* gp = src + (ok ? gr * (long long)ld : 0) + k0 + kc * 8;
            cp_async16(sb + (uint32_t)mat * 8192 + swz_off(row, kc), gp, ok);
        }
        CP_COMMIT();
    };

    auto compute_stage = [&](int it) {
        const uint32_t sb = sbase + (uint32_t)(it % 3) * STAGE_BYTES;
        #pragma unroll
        for (int ks = 0; ks < 2; ks++) {
            const int kc0 = ks * 2;
            uint32_t ah[4][4], al[4][4], bh[4][2], bl[4][2];
            const int arow = lane & 15;
            const int akc  = kc0 + (lane >> 4);
            #pragma unroll
            for (int i = 0; i < 4; i++) {
                uint32_t off = swz_off(warp_m + i * 16 + arow, akc);
                LDSM_X4(ah[i], sb + off);
                LDSM_X4(al[i], sb + 8192 + off);
            }
            const int brow = ((lane >> 4) << 3) + (lane & 7);
            const int bkc  = kc0 + ((lane >> 3) & 1);
            #pragma unroll
            for (int j = 0; j < 2; j++) {
                uint32_t r[4];
                uint32_t off = swz_off(warp_n + j * 16 + brow, bkc);
                LDSM_X4(r, sb + 16384 + off);
                bh[2*j][0] = r[0]; bh[2*j][1] = r[1];
                bh[2*j+1][0] = r[2]; bh[2*j+1][1] = r[3];
                LDSM_X4(r, sb + 24576 + off);
                bl[2*j][0] = r[0]; bl[2*j][1] = r[1];
                bl[2*j+1][0] = r[2]; bl[2*j+1][1] = r[3];
            }
            #pragma unroll
            for (int i = 0; i < 4; i++)
                #pragma unroll
                for (int j = 0; j < 4; j++) {
                    mma16816(acc[i][j], ah[i], bh[j]);
                    mma16816(acc[i][j], ah[i], bl[j]);
                    mma16816(acc[i][j], al[i], bh[j]);
                }
        }
    };

    load_stage(0);
    if (nCh > 1) load_stage(1);
    for (int it = 0; it < nCh; it++) {
        if (it + 1 < nCh) CP_WAIT1(); else CP_WAIT0();
        __syncthreads();
        if (it + 2 < nCh) load_stage(it + 2);
        compute_stage(it);
    }

    // ---- epilogue (paired loads/stores when alignment allows) ----
    const int tm = lane >> 2;
    const int tn = (lane & 3) * 2;
    const bool evenld = ((ldc & 1) == 0) && ((sC & 1LL) == 0LL);
    #pragma unroll
    for (int i = 0; i < 4; i++) {
        #pragma unroll
        for (int half = 0; half < 2; half++) {
            long long m = m0 + warp_m + i * 16 + tm + half * 8;
            if (m >= M) continue;
            const long long base = (long long)bz * sC + m * (long long)ldc;
            #pragma unroll
            for (int j = 0; j < 4; j++) {
                long long n = n0 + warp_n + j * 8 + tn;
                if (n >= Npad) continue;
                float v0 = acc[i][j][half * 2];
                float v1 = acc[i][j][half * 2 + 1];
                const bool pair = evenld && (n + 1 < Npad);
                float r0v = 0.f, r1v = 0.f;
                if (RESID) {
                    const long long rbase = (long long)bz * sR + m * (long long)ldc;
                    if (pair && (n + 1 < N)) {
                        float2 rv = *(const float2*)(resid + rbase + n);
                        r0v = rv.x; r1v = rv.y;
                    } else {
                        if (n < N) r0v = resid[rbase + n];
                        if (n + 1 < N) r1v = resid[rbase + n + 1];
                    }
                }
                float b0v = 0.f, b1v = 0.f;
                if (bias) {
                    if (n + 1 < N) {      // n always even, N even -> pairable
                        float2 bv = *(const float2*)(bias + n);
                        b0v = bv.x; b1v = bv.y;
                    } else if (n < N) b0v = bias[n];
                }
                if (n < N) {
                    v0 += b0v;
                    v0 *= alpha;
                    if (GELU) v0 = 0.5f * v0 * (1.0f + erff(v0 * 0.70710678118654752440f));
                    if (RESID) v0 += r0v;
                } else v0 = 0.f;
                if (n + 1 < N) {
                    v1 += b1v;
                    v1 *= alpha;
                    if (GELU) v1 = 0.5f * v1 * (1.0f + erff(v1 * 0.70710678118654752440f));
                    if (RESID) v1 += r1v;
                } else v1 = 0.f;
                if (WF32) {
                    if (pair) *(float2*)(Cf + base + n) = make_float2(v0, v1);
                    else { Cf[base + n] = v0; if (n + 1 < Npad) Cf[base + n + 1] = v1; }
                }
                if (WSPLIT) {
                    __nv_bfloat16 h0, l0, h1, l1;
                    split_f(v0, h0, l0); split_f(v1, h1, l1);
                    if (pair) {
                        __nv_bfloat162 hp; hp.x = h0; hp.y = h1;
                        __nv_bfloat162 lp; lp.x = l0; lp.y = l1;
                        *(__nv_bfloat162*)(Ch + base + n) = hp;
                        *(__nv_bfloat162*)(Cl + base + n) = lp;
                    } else {
                        Ch[base + n] = h0; Cl[base + n] = l0;
                        if (n + 1 < Npad) { Ch[base + n + 1] = h1; Cl[base + n + 1] = l1; }
                    }
                }
            }
        }
    }
}

// ---------------- LN body (192 threads, float4 / bf16x2) ----------------
__device__ __forceinline__ void ln_body(long long row,
                                        const float* __restrict__ x,
                                        const float* __restrict__ w,
                                        const float* __restrict__ b,
                                        __nv_bfloat16* __restrict__ oh,
                                        __nv_bfloat16* __restrict__ ol) {
    const float4* xr = (const float4*)(x + row * CC);
    const int t = threadIdx.x;              // 0..191
    float4 v4 = xr[t];
    float s  = v4.x + v4.y + v4.z + v4.w;
    float ss = v4.x * v4.x + v4.y * v4.y + v4.z * v4.z + v4.w * v4.w;
    __shared__ float r0[32], r1[32];
    #pragma unroll
    for (int o = 16; o > 0; o >>= 1) {
        s  += __shfl_xor_sync(0xffffffffu, s, o);
        ss += __shfl_xor_sync(0xffffffffu, ss, o);
    }
    int lane = t & 31, wd = t >> 5;
    if (lane == 0) { r0[wd] = s; r1[wd] = ss; }
    __syncthreads();
    if (t < 32) {
        float a = (t < 6) ? r0[t] : 0.f;
        float c = (t < 6) ? r1[t] : 0.f;
        #pragma unroll
        for (int o = 16; o > 0; o >>= 1) {
            a += __shfl_xor_sync(0xffffffffu, a, o);
            c += __shfl_xor_sync(0xffffffffu, c, o);
        }
        if (t == 0) { r0[0] = a; r1[0] = c; }
    }
    __syncthreads();
    float mean = r0[0] / (float)CC;
    float inv = rsqrtf(r1[0] / (float)CC - mean * mean + 1e-5f);
    float4 w4 = ((const float4*)w)[t];
    float4 b4 = ((const float4*)b)[t];
    float o0 = (v4.x - mean) * inv * w4.x + b4.x;
    float o1 = (v4.y - mean) * inv * w4.y + b4.y;
    float o2 = (v4.z - mean) * inv * w4.z + b4.z;
    float o3 = (v4.w - mean) * inv * w4.w + b4.w;
    __nv_bfloat16 h0,l0,h1,l1,h2,l2,h3,l3;
    split_f(o0,h0,l0); split_f(o1,h1,l1); split_f(o2,h2,l2); split_f(o3,h3,l3);
    long long base = row * CC + (long long)t * 4;
    __nv_bfloat162 hp0; hp0.x = h0; hp0.y = h1;
    __nv_bfloat162 hp1; hp1.x = h2; hp1.y = h3;
    __nv_bfloat162 lp0; lp0.x = l0; lp0.y = l1;
    __nv_bfloat162 lp1; lp1.x = l2; lp1.y = l3;
    *(__nv_bfloat162*)(oh + base)     = hp0;
    *(__nv_bfloat162*)(oh + base + 2) = hp1;
    *(__nv_bfloat162*)(ol + base)     = lp0;
    *(__nv_bfloat162*)(ol + base + 2) = lp1;
}

// plain LN launch (for LN2)
__global__ void ln_split_kernel(const float* __restrict__ x,
                                const float* __restrict__ w,
                                const float* __restrict__ b,
                                __nv_bfloat16* __restrict__ oh,
                                __nv_bfloat16* __restrict__ ol) {
    ln_body(blockIdx.x, x, w, b, oh, ol);
}

// ---------------- fused prologue: LN1 blocks + weight-split blocks ----------
#define W0 ((long long)3*CC*CC)                  // qkv
#define W1 (W0 + (long long)CC*CC)               // +proj
#define W2 (W1 + (long long)HH*CC)               // +fc1
#define W3 (W2 + (long long)CC*HH)               // +fc2
#define SPLIT_BLOCKS 9216                        // W3/4 float4 / 192 threads

__global__ void prologue_kernel(const float* __restrict__ x,
                                const float* __restrict__ norm1_w,
                                const float* __restrict__ norm1_b,
                                __nv_bfloat16* __restrict__ h_h, __nv_bfloat16* __restrict__ h_l,
                                const float* __restrict__ qkv_w,
                                const float* __restrict__ proj_w,
                                const float* __restrict__ fc1_w,
                                const float* __restrict__ fc2_w,
                                __nv_bfloat16* __restrict__ qkv_h, __nv_bfloat16* __restrict__ qkv_l,
                                __nv_bfloat16* __restrict__ proj_h, __nv_bfloat16* __restrict__ proj_l,
                                __nv_bfloat16* __restrict__ fc1_h, __nv_bfloat16* __restrict__ fc1_l,
                                __nv_bfloat16* __restrict__ fc2_h, __nv_bfloat16* __restrict__ fc2_l) {
    if (blockIdx.x < MROWS) {
        ln_body(blockIdx.x, x, norm1_w, norm1_b, h_h, h_l);
        return;
    }
    long long i4 = (long long)(blockIdx.x - MROWS) * 192 + threadIdx.x;
    long long i = i4 * 4;
    const float* src; __nv_bfloat16 *oh, *ol; long long off;
    if (i < W0)      { src = qkv_w;  oh = qkv_h;  ol = qkv_l;  off = i; }
    else if (i < W1) { src = proj_w; oh = proj_h; ol = proj_l; off = i - W0; }
    else if (i < W2) { src = fc1_w;  oh = fc1_h;  ol = fc1_l;  off = i - W1; }
    else             { src = fc2_w;  oh = fc2_h;  ol = fc2_l;  off = i - W2; }
    float4 v = *(const float4*)(src + off);
    __nv_bfloat16 h0,l0,h1,l1,h2,l2,h3,l3;
    split_f(v.x,h0,l0); split_f(v.y,h1,l1); split_f(v.z,h2,l2); split_f(v.w,h3,l3);
    __nv_bfloat162 hp0; hp0.x = h0; hp0.y = h1;
    __nv_bfloat162 hp1; hp1.x = h2; hp1.y = h3;
    __nv_bfloat162 lp0; lp0.x = l0; lp0.y = l1;
    __nv_bfloat162 lp1; lp1.x = l2; lp1.y = l3;
    *(__nv_bfloat162*)(oh + off)     = hp0;
    *(__nv_bfloat162*)(oh + off + 2) = hp1;
    *(__nv_bfloat162*)(ol + off)     = lp0;
    *(__nv_bfloat162*)(ol + off + 2) = lp1;
}

// -------- softmax over hi/lo score rows (288 threads: one bf16x2 pair each) --
__global__ void softmax_split_kernel(__nv_bfloat16* __restrict__ sh,
                                     __nv_bfloat16* __restrict__ sl,
                                     float* __restrict__ tok) {
    long long row = blockIdx.x;
    __nv_bfloat162* rh2 = (__nv_bfloat162*)(sh + row * NPAD);
    __nv_bfloat162* rl2 = (__nv_bfloat162*)(sl + row * NPAD);
    __nv_bfloat16* rh = sh + row * NPAD;
    __nv_bfloat16* rl = sl + row * NPAD;
    int t = (int)(row % NN);
    int b = (int)(row / NN);
    __shared__ float buf[NN];
    __shared__ float red[32];
    const int tx = threadIdx.x;              // 0..287
    int lane = tx & 31, wd = tx >> 5;
    int nw = blockDim.x >> 5;                // 9

    float a, c;
    {
        __nv_bfloat162 h2 = rh2[tx];
        __nv_bfloat162 l2 = rl2[tx];
        a = __bfloat162float(h2.x) + __bfloat162float(l2.x);
        c = __bfloat162float(h2.y) + __bfloat162float(l2.y);
        buf[2*tx] = a; buf[2*tx+1] = c;
    }
    float mx = fmaxf(a, c);
    if (tx == 0) {
        float v = __bfloat162float(rh[NN-1]) + __bfloat162float(rl[NN-1]);
        buf[NN-1] = v; mx = fmaxf(mx, v);
    }
    #pragma unroll
    for (int o = 16; o > 0; o >>= 1) mx = fmaxf(mx, __shfl_xor_sync(0xffffffffu, mx, o));
    if (lane == 0) red[wd] = mx;
    __syncthreads();
    if (tx < 32) {
        float v = (tx < nw) ? red[tx] : -1e30f;
        #pragma unroll
        for (int o = 16; o > 0; o >>= 1) v = fmaxf(v, __shfl_xor_sync(0xffffffffu, v, o));
        if (tx == 0) red[0] = v;
    }
    __syncthreads();
    mx = red[0];
    __syncthreads();

    float s = 0.f;
    for (int i = tx; i < NN; i += blockDim.x) {
        float e = __expf(buf[i] - mx); buf[i] = e; s += e;
    }
    #pragma unroll
    for (int o = 16; o > 0; o >>= 1) s += __shfl_xor_sync(0xffffffffu, s, o);
    if (lane == 0) red[wd] = s;
    __syncthreads();
    if (tx < 32) {
        float v = (tx < nw) ? red[tx] : 0.f;
        #pragma unroll
        for (int o = 16; o > 0; o >>= 1) v += __shfl_xor_sync(0xffffffffu, v, o);
        if (tx == 0) red[0] = v;
    }
    __syncthreads();
    float inv = 1.0f / red[0];
    {
        float pa = buf[2*tx] * inv;
        float pc = buf[2*tx+1] * inv;
        __nv_bfloat16 ha, la, hc, lc;
        split_f(pa, ha, la); split_f(pc, hc, lc);
        __nv_bfloat162 hp; hp.x = ha; hp.y = hc;
        __nv_bfloat162 lp; lp.x = la; lp.y = lc;
        rh2[tx] = hp; rl2[tx] = lp;
        if (t == 0) {
            if (2*tx >= 1) tok[(long long)b * (NN - 1) + (2*tx - 1)] = pa;
            tok[(long long)b * (NN - 1) + (2*tx)] = pc;
        }
    }
    if (tx == 0) {
        float v = buf[NN-1] * inv;
        __nv_bfloat16 h, l; split_f(v, h, l);
        rh[NN-1] = h; rl[NN-1] = l;
        if (t == 0) tok[(long long)b * (NN - 1) + (NN - 2)] = v;
    }
}

// ---------------- launch ----------------
extern "C" void kernel_launch(void* const* d_in, const int* in_sizes, int n_in,
                              void* d_out, int out_size) {
    const float* x       = (const float*)d_in[0];
    const float* norm1_w = (const float*)d_in[1];
    const float* norm1_b = (const float*)d_in[2];
    const float* qkv_w   = (const float*)d_in[3];
    const float* proj_w  = (const float*)d_in[4];
    const float* proj_b  = (const float*)d_in[5];
    const float* norm2_w = (const float*)d_in[6];
    const float* norm2_b = (const float*)d_in[7];
    const float* fc1_w   = (const float*)d_in[8];
    const float* fc1_b   = (const float*)d_in[9];
    const float* fc2_w   = (const float*)d_in[10];
    const float* fc2_b   = (const float*)d_in[11];

    float* out_x    = (float*)d_out;
    float* out_attn = out_x + OUT_X_ELEMS;

    __nv_bfloat16 *h_hi, *h_lo, *wqkv_hi, *wqkv_lo, *wproj_hi, *wproj_lo;
    __nv_bfloat16 *wfc1_hi, *wfc1_lo, *wfc2_hi, *wfc2_lo;
    __nv_bfloat16 *qk_hi, *qk_lo, *attn_hi, *attn_lo, *vT_hi, *vT_lo;
    __nv_bfloat16 *yt_hi, *yt_lo, *m1_hi, *m1_lo, *f1_hi, *f1_lo;
    float *x2;
    cudaGetSymbolAddress((void**)&h_hi, g_h_hi);   cudaGetSymbolAddress((void**)&h_lo, g_h_lo);
    cudaGetSymbolAddress((void**)&wqkv_hi, g_wqkv_hi); cudaGetSymbolAddress((void**)&wqkv_lo, g_wqkv_lo);
    cudaGetSymbolAddress((void**)&wproj_hi, g_wproj_hi); cudaGetSymbolAddress((void**)&wproj_lo, g_wproj_lo);
    cudaGetSymbolAddress((void**)&wfc1_hi, g_wfc1_hi); cudaGetSymbolAddress((void**)&wfc1_lo, g_wfc1_lo);
    cudaGetSymbolAddress((void**)&wfc2_hi, g_wfc2_hi); cudaGetSymbolAddress((void**)&wfc2_lo, g_wfc2_lo);
    cudaGetSymbolAddress((void**)&qk_hi, g_qk_hi); cudaGetSymbolAddress((void**)&qk_lo, g_qk_lo);
    cudaGetSymbolAddress((void**)&attn_hi, g_attn_hi); cudaGetSymbolAddress((void**)&attn_lo, g_attn_lo);
    cudaGetSymbolAddress((void**)&vT_hi, g_vT_hi); cudaGetSymbolAddress((void**)&vT_lo, g_vT_lo);
    cudaGetSymbolAddress((void**)&yt_hi, g_yt_hi); cudaGetSymbolAddress((void**)&yt_lo, g_yt_lo);
    cudaGetSymbolAddress((void**)&x2, g_x2);
    cudaGetSymbolAddress((void**)&m1_hi, g_m1_hi); cudaGetSymbolAddress((void**)&m1_lo, g_m1_lo);
    cudaGetSymbolAddress((void**)&f1_hi, g_f1_hi); cudaGetSymbolAddress((void**)&f1_lo, g_f1_lo);

    cudaFuncSetAttribute(mma_gemm<false,false,false,true>,  cudaFuncAttributeMaxDynamicSharedMemorySize, SMEM_BYTES);
    cudaFuncSetAttribute(mma_gemm<false,false,true,false>,  cudaFuncAttributeMaxDynamicSharedMemorySize, SMEM_BYTES);
    cudaFuncSetAttribute(mma_gemm<true,false,false,true>,   cudaFuncAttributeMaxDynamicSharedMemorySize, SMEM_BYTES);
    cudaFuncSetAttribute(mma_gemm<false,true,true,false>,   cudaFuncAttributeMaxDynamicSharedMemorySize, SMEM_BYTES);

    const float scale = 0.03608439182435161f; // 768^-0.5

    // 0+1) fused prologue: LN1 (MROWS blocks) + weight split (9216 blocks)
    prologue_kernel<<<MROWS + SPLIT_BLOCKS, 192>>>(
        x, norm1_w, norm1_b, h_hi, h_lo,
        qkv_w, proj_w, fc1_w, fc2_w,
        wqkv_hi, wqkv_lo, wproj_hi, wproj_lo,
        wfc1_hi, wfc1_lo, wfc2_hi, wfc2_lo);

    // 2) qk = h @ [wq;wk]^T  -> hi/lo  (N = 2*CC)
    mma_gemm<false,false,false,true><<<dim3(12, 145, 1), 256, SMEM_BYTES>>>(
        h_hi, h_lo, CC, 0, wqkv_hi, wqkv_lo, CC, 0,
        nullptr, qk_hi, qk_lo, 2*CC, 0,
        MROWS, 2*CC, 2*CC, CC, nullptr, 1.f, nullptr, 0);

    // 3) vT[c,t] = w_v[c,:]·h[t,:] per batch -> hi/lo, columns padded to NPAD
    mma_gemm<false,false,false,true><<<dim3(5, 6, BB), 256, SMEM_BYTES>>>(
        wqkv_hi + (size_t)2*CC*CC, wqkv_lo + (size_t)2*CC*CC, CC, 0,
        h_hi, h_lo, CC, (long long)NN*CC,
        nullptr, vT_hi, vT_lo, NPAD, (long long)CC*NPAD,
        CC, NN, NPAD, CC, nullptr, 1.f, nullptr, 0);

    // 4) scores = scale * q @ k^T per batch -> bf16 hi/lo (pads zero-filled)
    mma_gemm<false,false,false,true><<<dim3(5, 5, BB), 256, SMEM_BYTES>>>(
        qk_hi, qk_lo, 2*CC, (long long)NN*2*CC,
        qk_hi + CC, qk_lo + CC, 2*CC, (long long)NN*2*CC,
        nullptr, attn_hi, attn_lo, NPAD, (long long)NN*NPAD,
        NN, NN, NPAD, CC, nullptr, scale, nullptr, 0);

    // 5) softmax over hi/lo rows in place + token_attn slice (288 threads)
    softmax_split_kernel<<<MROWS, 288>>>(attn_hi, attn_lo, out_attn);

    // 6) yt[c,t] = sum_m vT[c,m]·attnP[t,m] per batch -> hi/lo ([CC][NN] dense)
    mma_gemm<false,false,false,true><<<dim3(5, 6, BB), 256, SMEM_BYTES>>>(
        vT_hi, vT_lo, NPAD, (long long)CC*NPAD,
        attn_hi, attn_lo, NPAD, (long long)NN*NPAD,
        nullptr, yt_hi, yt_lo, NN, (long long)CC*NN,
        CC, NN, NN, NPAD, nullptr, 1.f, nullptr, 0);

    // 7) x2 = 2*(yt_flat @ proj_w^T + proj_b) -> f32
    mma_gemm<false,false,true,false><<<dim3(6, 145, 1), 256, SMEM_BYTES>>>(
        yt_hi, yt_lo, CC, 0, wproj_hi, wproj_lo, CC, 0,
        x2, nullptr, nullptr, CC, 0,
        MROWS, CC, CC, CC, proj_b, 2.f, nullptr, 0);

    // 8) LN2 -> m1 hi/lo
    ln_split_kernel<<<MROWS, 192>>>(x2, norm2_w, norm2_b, m1_hi, m1_lo);

    // 9) f1 = gelu(m1 @ fc1_w^T + fc1_b) -> hi/lo
    mma_gemm<true,false,false,true><<<dim3(24, 145, 1), 256, SMEM_BYTES>>>(
        m1_hi, m1_lo, CC, 0, wfc1_hi, wfc1_lo, CC, 0,
        nullptr, f1_hi, f1_lo, HH, 0,
        MROWS, HH, HH, CC, fc1_b, 1.f, nullptr, 0);

    // 10) out_x = x2 + f1 @ fc2_w^T + fc2_b
    mma_gemm<false,true,true,false><<<dim3(6, 145, 1), 256, SMEM_BYTES>>>(
        f1_hi, f1_lo, HH, 0, wfc2_hi, wfc2_lo, HH, 0,
        out_x, nullptr, nullptr, CC, 0,
        MROWS, CC, CC, HH, fc2_b, 1.f, x2, 0);
}

// round 16
// speedup vs baseline: 1.0389x; 1.0017x over previous
#include <cuda_runtime.h>
#include <cuda_bf16.h>
#include <math.h>
#include <stdint.h>

// Problem dims
#define BB 32
#define NN 577
#define CC 768
#define HH 3072
#define MROWS (BB*NN)            // 18464
#define NPAD 608                 // 577 padded to multiple of 32
#define OUT_X_ELEMS ((long long)MROWS*CC)
#define OUT_ATTN_ELEMS (BB*(NN-1))
#define INV_CC 0.00130208333333333333f   // 1/768

// ---------------- helpers ----------------
__device__ __forceinline__ uint32_t smem_u32(const void* p) {
    uint32_t a;
    asm("{ .reg .u64 t; cvta.to.shared.u64 t, %1; cvt.u32.u64 %0, t; }" : "=r"(a) : "l"(p));
    return a;
}

#define LDSM_X4(r, a) \
    asm volatile("ldmatrix.sync.aligned.m8n8.x4.shared.b16 {%0,%1,%2,%3}, [%4];" \
        : "=r"((r)[0]),"=r"((r)[1]),"=r"((r)[2]),"=r"((r)[3]) : "r"(a))

__device__ __forceinline__ void mma16816(float* c, const uint32_t* a, const uint32_t* b) {
    asm volatile("mma.sync.aligned.m16n8k16.row.col.f32.bf16.bf16.f32 "
        "{%0,%1,%2,%3}, {%4,%5,%6,%7}, {%8,%9}, {%0,%1,%2,%3};"
        : "+f"(c[0]),"+f"(c[1]),"+f"(c[2]),"+f"(c[3])
        : "r"(a[0]),"r"(a[1]),"r"(a[2]),"r"(a[3]),"r"(b[0]),"r"(b[1]));
}

__device__ __forceinline__ void cp_async16(uint32_t dst, const void* src, int srcsz) {
    asm volatile("cp.async.cg.shared.global [%0], [%1], 16, %2;"
        :: "r"(dst), "l"(src), "r"(srcsz));
}
#define CP_COMMIT() asm volatile("cp.async.commit_group;")
#define CP_WAIT0()  asm volatile("cp.async.wait_group 0;")
#define CP_WAIT1()  asm volatile("cp.async.wait_group 1;")

// smem tile: 128 rows x 64B (32 bf16). XOR swizzle on 16B chunks.
__device__ __forceinline__ uint32_t swz_off(int row, int kc) {
    int c = kc ^ (row & 3) ^ ((row >> 2) & 1);
    return (uint32_t)(row * 64 + c * 16);
}

__device__ __forceinline__ void split_f(float v, __nv_bfloat16& h, __nv_bfloat16& l) {
    h = __float2bfloat16(v);
    l = __float2bfloat16(v - __bfloat162float(h));
}

// ---------------- scratch ----------------
__device__ __nv_bfloat16 g_h_hi[(size_t)MROWS*CC],   g_h_lo[(size_t)MROWS*CC];
__device__ __nv_bfloat16 g_wqkv_hi[(size_t)3*CC*CC], g_wqkv_lo[(size_t)3*CC*CC];
__device__ __nv_bfloat16 g_wproj_hi[(size_t)CC*CC],  g_wproj_lo[(size_t)CC*CC];
__device__ __nv_bfloat16 g_wfc1_hi[(size_t)HH*CC],   g_wfc1_lo[(size_t)HH*CC];
__device__ __nv_bfloat16 g_wfc2_hi[(size_t)CC*HH],   g_wfc2_lo[(size_t)CC*HH];
__device__ __nv_bfloat16 g_qk_hi[(size_t)MROWS*2*CC], g_qk_lo[(size_t)MROWS*2*CC];
__device__ __nv_bfloat16 g_attn_hi[(size_t)BB*NN*NPAD], g_attn_lo[(size_t)BB*NN*NPAD];
__device__ __nv_bfloat16 g_vT_hi[(size_t)BB*CC*NPAD],   g_vT_lo[(size_t)BB*CC*NPAD];
__device__ __nv_bfloat16 g_yt_hi[(size_t)MROWS*CC],  g_yt_lo[(size_t)MROWS*CC];
__device__ float         g_x2[(size_t)MROWS*CC];
__device__ __nv_bfloat16 g_m1_hi[(size_t)MROWS*CC],  g_m1_lo[(size_t)MROWS*CC];
__device__ __nv_bfloat16 g_f1_hi[(size_t)MROWS*HH],  g_f1_lo[(size_t)MROWS*HH];

// ============= mma.sync bf16x3 GEMM (8 warps, 64x32 warp tile, 3-stage) ====
#define STAGE_BYTES 32768
#define SMEM_BYTES  (3*STAGE_BYTES)

template<bool GELU, bool RESID, bool WF32, bool WSPLIT>
__global__ void __launch_bounds__(256, 2) mma_gemm(
    const __nv_bfloat16* __restrict__ Ah, const __nv_bfloat16* __restrict__ Al,
    int lda, long long sA,
    const __nv_bfloat16* __restrict__ Bh, const __nv_bfloat16* __restrict__ Bl,
    int ldb, long long sB,
    float* __restrict__ Cf, __nv_bfloat16* __restrict__ Ch, __nv_bfloat16* __restrict__ Cl,
    int ldc, long long sC,
    int M, int N, int Npad, int K,
    const float* __restrict__ bias, float alpha,
    const float* __restrict__ resid, long long sR)
{
    extern __shared__ char smem[];
    const uint32_t sbase = smem_u32(smem);
    const int tid = threadIdx.x;
    const int wid = tid >> 5, lane = tid & 31;
    const int bz = blockIdx.z;
    const long long m0 = (long long)blockIdx.y * 128;
    const long long n0 = (long long)blockIdx.x * 128;
    const int warp_m = (wid & 1) * 64;
    const int warp_n = (wid >> 1) * 32;

    Ah += bz * sA; Al += bz * sA;
    Bh += bz * sB; Bl += bz * sB;

    const int nCh = K >> 5;

    float acc[4][4][4];
    #pragma unroll
    for (int i = 0; i < 4; i++)
        #pragma unroll
        for (int j = 0; j < 4; j++)
            #pragma unroll
            for (int e = 0; e < 4; e++) acc[i][j][e] = 0.f;

    auto load_stage = [&](int it) {
        const uint32_t sb = sbase + (uint32_t)(it % 3) * STAGE_BYTES;
        const long long k0 = (long long)it << 5;
        #pragma unroll
        for (int u = 0; u < 8; u++) {
            int idx = u * 256 + tid;
            int mat = idx >> 9;        // 0:Ah 1:Al 2:Bh 3:Bl
            int rem = idx & 511;
            int row = rem >> 2;
            int kc  = rem & 3;
            const __nv_bfloat16* src = (mat == 0) ? Ah : (mat == 1) ? Al
                                      : (mat == 2) ? Bh : Bl;
            long long r0 = (mat < 2) ? m0 : n0;
            int rt = (mat < 2) ? M : N;
            int ld = (mat < 2) ? lda : ldb;
            long long gr = r0 + row;
            int ok = (gr < rt) ? 16 : 0;
            const __nv_bfloat16* gp = src + (ok ? gr * (long long)ld : 0) + k0 + kc * 8;
            cp_async16(sb + (uint32_t)mat * 8192 + swz_off(row, kc), gp, ok);
        }
        CP_COMMIT();
    };

    auto compute_stage = [&](int it) {
        const uint32_t sb = sbase + (uint32_t)(it % 3) * STAGE_BYTES;
        #pragma unroll
        for (int ks = 0; ks < 2; ks++) {
            const int kc0 = ks * 2;
            uint32_t ah[4][4], al[4][4], bh[4][2], bl[4][2];
            const int arow = lane & 15;
            const int akc  = kc0 + (lane >> 4);
            #pragma unroll
            for (int i = 0; i < 4; i++) {
                uint32_t off = swz_off(warp_m + i * 16 + arow, akc);
                LDSM_X4(ah[i], sb + off);
                LDSM_X4(al[i], sb + 8192 + off);
            }
            const int brow = ((lane >> 4) << 3) + (lane & 7);
            const int bkc  = kc0 + ((lane >> 3) & 1);
            #pragma unroll
            for (int j = 0; j < 2; j++) {
                uint32_t r[4];
                uint32_t off = swz_off(warp_n + j * 16 + brow, bkc);
                LDSM_X4(r, sb + 16384 + off);
                bh[2*j][0] = r[0]; bh[2*j][1] = r[1];
                bh[2*j+1][0] = r[2]; bh[2*j+1][1] = r[3];
                LDSM_X4(r, sb + 24576 + off);
                bl[2*j][0] = r[0]; bl[2*j][1] = r[1];
                bl[2*j+1][0] = r[2]; bl[2*j+1][1] = r[3];
            }
            #pragma unroll
            for (int i = 0; i < 4; i++)
                #pragma unroll
                for (int j = 0; j < 4; j++) {
                    mma16816(acc[i][j], ah[i], bh[j]);
                    mma16816(acc[i][j], ah[i], bl[j]);
                    mma16816(acc[i][j], al[i], bh[j]);
                }
        }
    };

    load_stage(0);
    if (nCh > 1) load_stage(1);
    for (int it = 0; it < nCh; it++) {
        if (it + 1 < nCh) CP_WAIT1(); else CP_WAIT0();
        __syncthreads();
        if (it + 2 < nCh) load_stage(it + 2);
        compute_stage(it);
    }

    // ---- epilogue (paired loads/stores when alignment allows) ----
    const int tm = lane >> 2;
    const int tn = (lane & 3) * 2;
    const bool evenld = ((ldc & 1) == 0) && ((sC & 1LL) == 0LL);
    #pragma unroll
    for (int i = 0; i < 4; i++) {
        #pragma unroll
        for (int half = 0; half < 2; half++) {
            long long m = m0 + warp_m + i * 16 + tm + half * 8;
            if (m >= M) continue;
            const long long base = (long long)bz * sC + m * (long long)ldc;
            #pragma unroll
            for (int j = 0; j < 4; j++) {
                long long n = n0 + warp_n + j * 8 + tn;
                if (n >= Npad) continue;
                float v0 = acc[i][j][half * 2];
                float v1 = acc[i][j][half * 2 + 1];
                const bool pair = evenld && (n + 1 < Npad);
                float r0v = 0.f, r1v = 0.f;
                if (RESID) {
                    const long long rbase = (long long)bz * sR + m * (long long)ldc;
                    if (pair && (n + 1 < N)) {
                        float2 rv = *(const float2*)(resid + rbase + n);
                        r0v = rv.x; r1v = rv.y;
                    } else {
                        if (n < N) r0v = resid[rbase + n];
                        if (n + 1 < N) r1v = resid[rbase + n + 1];
                    }
                }
                float b0v = 0.f, b1v = 0.f;
                if (bias) {
                    if (n + 1 < N) {
                        float2 bv = *(const float2*)(bias + n);
                        b0v = bv.x; b1v = bv.y;
                    } else if (n < N) b0v = bias[n];
                }
                if (n < N) {
                    v0 += b0v;
                    v0 *= alpha;
                    if (GELU) v0 = 0.5f * v0 * (1.0f + erff(v0 * 0.70710678118654752440f));
                    if (RESID) v0 += r0v;
                } else v0 = 0.f;
                if (n + 1 < N) {
                    v1 += b1v;
                    v1 *= alpha;
                    if (GELU) v1 = 0.5f * v1 * (1.0f + erff(v1 * 0.70710678118654752440f));
                    if (RESID) v1 += r1v;
                } else v1 = 0.f;
                if (WF32) {
                    if (pair) *(float2*)(Cf + base + n) = make_float2(v0, v1);
                    else { Cf[base + n] = v0; if (n + 1 < Npad) Cf[base + n + 1] = v1; }
                }
                if (WSPLIT) {
                    __nv_bfloat16 h0, l0, h1, l1;
                    split_f(v0, h0, l0); split_f(v1, h1, l1);
                    if (pair) {
                        __nv_bfloat162 hp; hp.x = h0; hp.y = h1;
                        __nv_bfloat162 lp; lp.x = l0; lp.y = l1;
                        *(__nv_bfloat162*)(Ch + base + n) = hp;
                        *(__nv_bfloat162*)(Cl + base + n) = lp;
                    } else {
                        Ch[base + n] = h0; Cl[base + n] = l0;
                        if (n + 1 < Npad) { Ch[base + n + 1] = h1; Cl[base + n + 1] = l1; }
                    }
                }
            }
        }
    }
}

// ---------------- LN body (192 threads, float4 / bf16x2) ----------------
__device__ __forceinline__ void ln_body(long long row,
                                        const float* __restrict__ x,
                                        const float* __restrict__ w,
                                        const float* __restrict__ b,
                                        __nv_bfloat16* __restrict__ oh,
                                        __nv_bfloat16* __restrict__ ol) {
    const float4* xr = (const float4*)(x + row * CC);
    const int t = threadIdx.x;              // 0..191
    float4 v4 = xr[t];
    float s  = v4.x + v4.y + v4.z + v4.w;
    float ss = v4.x * v4.x + v4.y * v4.y + v4.z * v4.z + v4.w * v4.w;
    __shared__ float r0[32], r1[32];
    #pragma unroll
    for (int o = 16; o > 0; o >>= 1) {
        s  += __shfl_xor_sync(0xffffffffu, s, o);
        ss += __shfl_xor_sync(0xffffffffu, ss, o);
    }
    int lane = t & 31, wd = t >> 5;
    if (lane == 0) { r0[wd] = s; r1[wd] = ss; }
    __syncthreads();
    if (t < 32) {
        float a = (t < 6) ? r0[t] : 0.f;
        float c = (t < 6) ? r1[t] : 0.f;
        #pragma unroll
        for (int o = 16; o > 0; o >>= 1) {
            a += __shfl_xor_sync(0xffffffffu, a, o);
            c += __shfl_xor_sync(0xffffffffu, c, o);
        }
        if (t == 0) { r0[0] = a; r1[0] = c; }
    }
    __syncthreads();
    float mean = r0[0] * INV_CC;
    float inv = rsqrtf(r1[0] * INV_CC - mean * mean + 1e-5f);
    float4 w4 = ((const float4*)w)[t];
    float4 b4 = ((const float4*)b)[t];
    float o0 = (v4.x - mean) * inv * w4.x + b4.x;
    float o1 = (v4.y - mean) * inv * w4.y + b4.y;
    float o2 = (v4.z - mean) * inv * w4.z + b4.z;
    float o3 = (v4.w - mean) * inv * w4.w + b4.w;
    __nv_bfloat16 h0,l0,h1,l1,h2,l2,h3,l3;
    split_f(o0,h0,l0); split_f(o1,h1,l1); split_f(o2,h2,l2); split_f(o3,h3,l3);
    long long base = row * CC + (long long)t * 4;
    __nv_bfloat162 hp0; hp0.x = h0; hp0.y = h1;
    __nv_bfloat162 hp1; hp1.x = h2; hp1.y = h3;
    __nv_bfloat162 lp0; lp0.x = l0; lp0.y = l1;
    __nv_bfloat162 lp1; lp1.x = l2; lp1.y = l3;
    *(__nv_bfloat162*)(oh + base)     = hp0;
    *(__nv_bfloat162*)(oh + base + 2) = hp1;
    *(__nv_bfloat162*)(ol + base)     = lp0;
    *(__nv_bfloat162*)(ol + base + 2) = lp1;
}

// plain LN launch (for LN2)
__global__ void ln_split_kernel(const float* __restrict__ x,
                                const float* __restrict__ w,
                                const float* __restrict__ b,
                                __nv_bfloat16* __restrict__ oh,
                                __nv_bfloat16* __restrict__ ol) {
    ln_body(blockIdx.x, x, w, b, oh, ol);
}

// ---------------- fused prologue: LN1 blocks + weight-split blocks ----------
#define W0 ((long long)3*CC*CC)                  // qkv
#define W1 (W0 + (long long)CC*CC)               // +proj
#define W2 (W1 + (long long)HH*CC)               // +fc1
#define W3 (W2 + (long long)CC*HH)               // +fc2
#define SPLIT_BLOCKS 9216                        // W3/4 float4 / 192 threads

__global__ void prologue_kernel(const float* __restrict__ x,
                                const float* __restrict__ norm1_w,
                                const float* __restrict__ norm1_b,
                                __nv_bfloat16* __restrict__ h_h, __nv_bfloat16* __restrict__ h_l,
                                const float* __restrict__ qkv_w,
                                const float* __restrict__ proj_w,
                                const float* __restrict__ fc1_w,
                                const float* __restrict__ fc2_w,
                                __nv_bfloat16* __restrict__ qkv_h, __nv_bfloat16* __restrict__ qkv_l,
                                __nv_bfloat16* __restrict__ proj_h, __nv_bfloat16* __restrict__ proj_l,
                                __nv_bfloat16* __restrict__ fc1_h, __nv_bfloat16* __restrict__ fc1_l,
                                __nv_bfloat16* __restrict__ fc2_h, __nv_bfloat16* __restrict__ fc2_l) {
    if (blockIdx.x < MROWS) {
        ln_body(blockIdx.x, x, norm1_w, norm1_b, h_h, h_l);
        return;
    }
    long long i4 = (long long)(blockIdx.x - MROWS) * 192 + threadIdx.x;
    long long i = i4 * 4;
    const float* src; __nv_bfloat16 *oh, *ol; long long off;
    if (i < W0)      { src = qkv_w;  oh = qkv_h;  ol = qkv_l;  off = i; }
    else if (i < W1) { src = proj_w; oh = proj_h; ol = proj_l; off = i - W0; }
    else if (i < W2) { src = fc1_w;  oh = fc1_h;  ol = fc1_l;  off = i - W1; }
    else             { src = fc2_w;  oh = fc2_h;  ol = fc2_l;  off = i - W2; }
    float4 v = *(const float4*)(src + off);
    __nv_bfloat16 h0,l0,h1,l1,h2,l2,h3,l3;
    split_f(v.x,h0,l0); split_f(v.y,h1,l1); split_f(v.z,h2,l2); split_f(v.w,h3,l3);
    __nv_bfloat162 hp0; hp0.x = h0; hp0.y = h1;
    __nv_bfloat162 hp1; hp1.x = h2; hp1.y = h3;
    __nv_bfloat162 lp0; lp0.x = l0; lp0.y = l1;
    __nv_bfloat162 lp1; lp1.x = l2; lp1.y = l3;
    *(__nv_bfloat162*)(oh + off)     = hp0;
    *(__nv_bfloat162*)(oh + off + 2) = hp1;
    *(__nv_bfloat162*)(ol + off)     = lp0;
    *(__nv_bfloat162*)(ol + off + 2) = lp1;
}

// -------- softmax over hi/lo score rows (288 threads, 2 rows per block) -----
#define SMAX_RPB 2
__device__ __forceinline__ void softmax_row(long long row,
                                            __nv_bfloat16* __restrict__ sh,
                                            __nv_bfloat16* __restrict__ sl,
                                            float* __restrict__ tok,
                                            float* buf, float* red) {
    __nv_bfloat162* rh2 = (__nv_bfloat162*)(sh + row * NPAD);
    __nv_bfloat162* rl2 = (__nv_bfloat162*)(sl + row * NPAD);
    __nv_bfloat16* rh = sh + row * NPAD;
    __nv_bfloat16* rl = sl + row * NPAD;
    int t = (int)(row % NN);
    int b = (int)(row / NN);
    const int tx = threadIdx.x;              // 0..287
    int lane = tx & 31, wd = tx >> 5;

    float a, c;
    {
        __nv_bfloat162 h2 = rh2[tx];
        __nv_bfloat162 l2 = rl2[tx];
        a = __bfloat162float(h2.x) + __bfloat162float(l2.x);
        c = __bfloat162float(h2.y) + __bfloat162float(l2.y);
        buf[2*tx] = a; buf[2*tx+1] = c;
    }
    float mx = fmaxf(a, c);
    if (tx == 0) {
        float v = __bfloat162float(rh[NN-1]) + __bfloat162float(rl[NN-1]);
        buf[NN-1] = v; mx = fmaxf(mx, v);
    }
    #pragma unroll
    for (int o = 16; o > 0; o >>= 1) mx = fmaxf(mx, __shfl_xor_sync(0xffffffffu, mx, o));
    if (lane == 0) red[wd] = mx;
    __syncthreads();
    if (tx < 32) {
        float v = (tx < 9) ? red[tx] : -1e30f;
        #pragma unroll
        for (int o = 16; o > 0; o >>= 1) v = fmaxf(v, __shfl_xor_sync(0xffffffffu, v, o));
        if (tx == 0) red[0] = v;
    }
    __syncthreads();
    mx = red[0];
    __syncthreads();

    float s = 0.f;
    for (int i = tx; i < NN; i += 288) {
        float e = __expf(buf[i] - mx); buf[i] = e; s += e;
    }
    #pragma unroll
    for (int o = 16; o > 0; o >>= 1) s += __shfl_xor_sync(0xffffffffu, s, o);
    if (lane == 0) red[wd] = s;
    __syncthreads();
    if (tx < 32) {
        float v = (tx < 9) ? red[tx] : 0.f;
        #pragma unroll
        for (int o = 16; o > 0; o >>= 1) v += __shfl_xor_sync(0xffffffffu, v, o);
        if (tx == 0) red[0] = v;
    }
    __syncthreads();
    float inv = 1.0f / red[0];
    {
        float pa = buf[2*tx] * inv;
        float pc = buf[2*tx+1] * inv;
        __nv_bfloat16 ha, la, hc, lc;
        split_f(pa, ha, la); split_f(pc, hc, lc);
        __nv_bfloat162 hp; hp.x = ha; hp.y = hc;
        __nv_bfloat162 lp; lp.x = la; lp.y = lc;
        rh2[tx] = hp; rl2[tx] = lp;
        if (t == 0) {
            if (2*tx >= 1) tok[(long long)b * (NN - 1) + (2*tx - 1)] = pa;
            tok[(long long)b * (NN - 1) + (2*tx)] = pc;
        }
    }
    if (tx == 0) {
        float v = buf[NN-1] * inv;
        __nv_bfloat16 h, l; split_f(v, h, l);
        rh[NN-1] = h; rl[NN-1] = l;
        if (t == 0) tok[(long long)b * (NN - 1) + (NN - 2)] = v;
    }
}

__global__ void softmax_split_kernel(__nv_bfloat16* __restrict__ sh,
                                     __nv_bfloat16* __restrict__ sl,
                                     float* __restrict__ tok) {
    __shared__ float buf[NN];
    __shared__ float red[32];
    long long row0 = (long long)blockIdx.x * SMAX_RPB;
    #pragma unroll
    for (int r = 0; r < SMAX_RPB; r++) {
        long long row = row0 + r;
        if (row < MROWS) {
            softmax_row(row, sh, sl, tok, buf, red);
            if (r + 1 < SMAX_RPB) __syncthreads();
        }
    }
}

// ---------------- launch ----------------
extern "C" void kernel_launch(void* const* d_in, const int* in_sizes, int n_in,
                              void* d_out, int out_size) {
    const float* x       = (const float*)d_in[0];
    const float* norm1_w = (const float*)d_in[1];
    const float* norm1_b = (const float*)d_in[2];
    const float* qkv_w   = (const float*)d_in[3];
    const float* proj_w  = (const float*)d_in[4];
    const float* proj_b  = (const float*)d_in[5];
    const float* norm2_w = (const float*)d_in[6];
    const float* norm2_b = (const float*)d_in[7];
    const float* fc1_w   = (const float*)d_in[8];
    const float* fc1_b   = (const float*)d_in[9];
    const float* fc2_w   = (const float*)d_in[10];
    const float* fc2_b   = (const float*)d_in[11];

    float* out_x    = (float*)d_out;
    float* out_attn = out_x + OUT_X_ELEMS;

    __nv_bfloat16 *h_hi, *h_lo, *wqkv_hi, *wqkv_lo, *wproj_hi, *wproj_lo;
    __nv_bfloat16 *wfc1_hi, *wfc1_lo, *wfc2_hi, *wfc2_lo;
    __nv_bfloat16 *qk_hi, *qk_lo, *attn_hi, *attn_lo, *vT_hi, *vT_lo;
    __nv_bfloat16 *yt_hi, *yt_lo, *m1_hi, *m1_lo, *f1_hi, *f1_lo;
    float *x2;
    cudaGetSymbolAddress((void**)&h_hi, g_h_hi);   cudaGetSymbolAddress((void**)&h_lo, g_h_lo);
    cudaGetSymbolAddress((void**)&wqkv_hi, g_wqkv_hi); cudaGetSymbolAddress((void**)&wqkv_lo, g_wqkv_lo);
    cudaGetSymbolAddress((void**)&wproj_hi, g_wproj_hi); cudaGetSymbolAddress((void**)&wproj_lo, g_wproj_lo);
    cudaGetSymbolAddress((void**)&wfc1_hi, g_wfc1_hi); cudaGetSymbolAddress((void**)&wfc1_lo, g_wfc1_lo);
    cudaGetSymbolAddress((void**)&wfc2_hi, g_wfc2_hi); cudaGetSymbolAddress((void**)&wfc2_lo, g_wfc2_lo);
    cudaGetSymbolAddress((void**)&qk_hi, g_qk_hi); cudaGetSymbolAddress((void**)&qk_lo, g_qk_lo);
    cudaGetSymbolAddress((void**)&attn_hi, g_attn_hi); cudaGetSymbolAddress((void**)&attn_lo, g_attn_lo);
    cudaGetSymbolAddress((void**)&vT_hi, g_vT_hi); cudaGetSymbolAddress((void**)&vT_lo, g_vT_lo);
    cudaGetSymbolAddress((void**)&yt_hi, g_yt_hi); cudaGetSymbolAddress((void**)&yt_lo, g_yt_lo);
    cudaGetSymbolAddress((void**)&x2, g_x2);
    cudaGetSymbolAddress((void**)&m1_hi, g_m1_hi); cudaGetSymbolAddress((void**)&m1_lo, g_m1_lo);
    cudaGetSymbolAddress((void**)&f1_hi, g_f1_hi); cudaGetSymbolAddress((void**)&f1_lo, g_f1_lo);

    cudaFuncSetAttribute(mma_gemm<false,false,false,true>,  cudaFuncAttributeMaxDynamicSharedMemorySize, SMEM_BYTES);
    cudaFuncSetAttribute(mma_gemm<false,false,true,false>,  cudaFuncAttributeMaxDynamicSharedMemorySize, SMEM_BYTES);
    cudaFuncSetAttribute(mma_gemm<true,false,false,true>,   cudaFuncAttributeMaxDynamicSharedMemorySize, SMEM_BYTES);
    cudaFuncSetAttribute(mma_gemm<false,true,true,false>,   cudaFuncAttributeMaxDynamicSharedMemorySize, SMEM_BYTES);

    const float scale = 0.03608439182435161f; // 768^-0.5

    // 0+1) fused prologue: LN1 (MROWS blocks) + weight split (9216 blocks)
    prologue_kernel<<<MROWS + SPLIT_BLOCKS, 192>>>(
        x, norm1_w, norm1_b, h_hi, h_lo,
        qkv_w, proj_w, fc1_w, fc2_w,
        wqkv_hi, wqkv_lo, wproj_hi, wproj_lo,
        wfc1_hi, wfc1_lo, wfc2_hi, wfc2_lo);

    // 2) qk = h @ [wq;wk]^T  -> hi/lo  (N = 2*CC)
    mma_gemm<false,false,false,true><<<dim3(12, 145, 1), 256, SMEM_BYTES>>>(
        h_hi, h_lo, CC, 0, wqkv_hi, wqkv_lo, CC, 0,
        nullptr, qk_hi, qk_lo, 2*CC, 0,
        MROWS, 2*CC, 2*CC, CC, nullptr, 1.f, nullptr, 0);

    // 3) vT[c,t] = w_v[c,:]·h[t,:] per batch -> hi/lo, columns padded to NPAD
    mma_gemm<false,false,false,true><<<dim3(5, 6, BB), 256, SMEM_BYTES>>>(
        wqkv_hi + (size_t)2*CC*CC, wqkv_lo + (size_t)2*CC*CC, CC, 0,
        h_hi, h_lo, CC, (long long)NN*CC,
        nullptr, vT_hi, vT_lo, NPAD, (long long)CC*NPAD,
        CC, NN, NPAD, CC, nullptr, 1.f, nullptr, 0);

    // 4) scores = scale * q @ k^T per batch -> bf16 hi/lo (pads zero-filled)
    mma_gemm<false,false,false,true><<<dim3(5, 5, BB), 256, SMEM_BYTES>>>(
        qk_hi, qk_lo, 2*CC, (long long)NN*2*CC,
        qk_hi + CC, qk_lo + CC, 2*CC, (long long)NN*2*CC,
        nullptr, attn_hi, attn_lo, NPAD, (long long)NN*NPAD,
        NN, NN, NPAD, CC, nullptr, scale, nullptr, 0);

    // 5) softmax over hi/lo rows in place + token_attn slice (2 rows/block)
    softmax_split_kernel<<<(MROWS + SMAX_RPB - 1) / SMAX_RPB, 288>>>(
        attn_hi, attn_lo, out_attn);

    // 6) yt[c,t] = sum_m vT[c,m]·attnP[t,m] per batch -> hi/lo ([CC][NN] dense)
    mma_gemm<false,false,false,true><<<dim3(5, 6, BB), 256, SMEM_BYTES>>>(
        vT_hi, vT_lo, NPAD, (long long)CC*NPAD,
        attn_hi, attn_lo, NPAD, (long long)NN*NPAD,
        nullptr, yt_hi, yt_lo, NN, (long long)CC*NN,
        CC, NN, NN, NPAD, nullptr, 1.f, nullptr, 0);

    // 7) x2 = 2*(yt_flat @ proj_w^T + proj_b) -> f32
    mma_gemm<false,false,true,false><<<dim3(6, 145, 1), 256, SMEM_BYTES>>>(
        yt_hi, yt_lo, CC, 0, wproj_hi, wproj_lo, CC, 0,
        x2, nullptr, nullptr, CC, 0,
        MROWS, CC, CC, CC, proj_b, 2.f, nullptr, 0);

    // 8) LN2 -> m1 hi/lo
    ln_split_kernel<<<MROWS, 192>>>(x2, norm2_w, norm2_b, m1_hi, m1_lo);

    // 9) f1 = gelu(m1 @ fc1_w^T + fc1_b) -> hi/lo
    mma_gemm<true,false,false,true><<<dim3(24, 145, 1), 256, SMEM_BYTES>>>(
        m1_hi, m1_lo, CC, 0, wfc1_hi, wfc1_lo, CC, 0,
        nullptr, f1_hi, f1_lo, HH, 0,
        MROWS, HH, HH, CC, fc1_b, 1.f, nullptr, 0);

    // 10) out_x = x2 + f1 @ fc2_w^T + fc2_b
    mma_gemm<false,true,true,false><<<dim3(6, 145, 1), 256, SMEM_BYTES>>>(
        f1_hi, f1_lo, HH, 0, wfc2_hi, wfc2_lo, HH, 0,
        out_x, nullptr, nullptr, CC, 0,
        MROWS, CC, CC, HH, fc2_b, 1.f, x2, 0);
}